// round 8
// baseline (speedup 1.0000x reference)
#include <cuda_runtime.h>
#include <cuda_bf16.h>
#include <cstddef>
#include <cstdint>
#include <math.h>

// Problem constants
#define BB 4
#define LSEQ 2048
#define DMODEL 1024
#define NH 16
#define HDIM 64
#define MROWS (BB * LSEQ)      // 8192
#define QKVN (3 * DMODEL)      // 3072

// Scratch (static device arrays; no allocation APIs allowed)
__device__ float g_qkv[(size_t)MROWS * QKVN];    // (B*L, 3D), tf32-rounded
__device__ float g_attn[(size_t)MROWS * DMODEL]; // (B*L, D), tf32-rounded
__device__ float g_x[(size_t)MROWS * DMODEL];    // x, tf32-rounded
__device__ float g_wqkv[(size_t)DMODEL * QKVN];  // w_qkv, tf32-rounded
__device__ float g_wproj[(size_t)DMODEL * DMODEL];

__device__ __forceinline__ float tf32r(float x) {
    float y;
    asm("cvt.rna.tf32.f32 %0, %1;" : "=f"(y) : "f"(x));
    return y;
}

__device__ __forceinline__ void mma_tf32(float* d, const uint32_t* a,
                                         const uint32_t* b) {
    asm volatile(
        "mma.sync.aligned.m16n8k8.row.col.f32.tf32.tf32.f32 "
        "{%0,%1,%2,%3}, {%4,%5,%6,%7}, {%8,%9}, {%0,%1,%2,%3};\n"
        : "+f"(d[0]), "+f"(d[1]), "+f"(d[2]), "+f"(d[3])
        : "r"(a[0]), "r"(a[1]), "r"(a[2]), "r"(a[3]), "r"(b[0]), "r"(b[1]));
}

__device__ __forceinline__ void cpa16(uint32_t dst_smem, const void* src) {
    asm volatile("cp.async.cg.shared.global [%0], [%1], 16;\n"
                 :: "r"(dst_smem), "l"(src));
}
__device__ __forceinline__ void cpa_commit() {
    asm volatile("cp.async.commit_group;\n");
}
template <int N>
__device__ __forceinline__ void cpa_wait() {
    asm volatile("cp.async.wait_group %0;\n" :: "n"(N));
}

// ---------------------------------------------------------------------------
// Elementwise tf32 pre-round (float4 grid-stride)
// ---------------------------------------------------------------------------
__global__ void round_tf32_kernel(const float4* __restrict__ in,
                                  float4* __restrict__ out, int n4)
{
    int i = blockIdx.x * blockDim.x + threadIdx.x;
    if (i < n4) {
        float4 v = in[i];
        v.x = tf32r(v.x); v.y = tf32r(v.y);
        v.z = tf32r(v.z); v.w = tf32r(v.w);
        out[i] = v;
    }
}

// ---------------------------------------------------------------------------
// TF32 tensor-core GEMM, cp.async double-buffered.
// C[M,N] = A[M,K] @ B[K,N] (+bias). Inputs already tf32-rounded.
// CTA tile 128x128x32, 8 warps (4 M x 2 N), warp tile 32x64.
// Smem per stage: As 128x36 (4608 fl) + Bs 32x136 (4352 fl) = 35840 B.
// ---------------------------------------------------------------------------
#define GBM 128
#define GBN 128
#define GBK 32
#define ASTR 36
#define BSTR 136
#define STAGE_FLOATS (GBM * ASTR + GBK * BSTR)
#define GEMM_SMEM_BYTES (2 * STAGE_FLOATS * (int)sizeof(float))

__global__ void __launch_bounds__(256, 2)
gemm_tf32_kernel(const float* __restrict__ A, const float* __restrict__ B,
                 float* __restrict__ C, int M, int N, int K,
                 const float* __restrict__ bias, int round_out)
{
    extern __shared__ float gsm[];

    const int tid = threadIdx.x;
    const int lane = tid & 31;
    const int warp = tid >> 5;
    const int wm = (warp & 3) * 32;
    const int wn = (warp >> 2) * 64;
    const int g = lane >> 2;
    const int t = lane & 3;

    const float* Ab = A + (size_t)blockIdx.y * GBM * K;
    const float* Bb = B + (size_t)blockIdx.x * GBN;

    const uint32_t smem0 = (uint32_t)__cvta_generic_to_shared(gsm);

    // per-thread copy coordinates (4 float4 for A, 4 for B)
    const int ar[4] = { (tid + 0) >> 3, (tid + 256) >> 3,
                        (tid + 512) >> 3, (tid + 768) >> 3 };
    const int ac = (tid & 7) * 4;
    const int br[4] = { (tid + 0) >> 5, (tid + 256) >> 5,
                        (tid + 512) >> 5, (tid + 768) >> 5 };
    const int bc = (tid & 31) * 4;

    auto load_stage = [&](int s, int k0) {
        uint32_t asb = smem0 + (uint32_t)(s * STAGE_FLOATS) * 4u;
        uint32_t bsb = asb + (uint32_t)(GBM * ASTR) * 4u;
#pragma unroll
        for (int p = 0; p < 4; p++)
            cpa16(asb + (uint32_t)(ar[p] * ASTR + ac) * 4u,
                  Ab + (size_t)ar[p] * K + k0 + ac);
#pragma unroll
        for (int p = 0; p < 4; p++)
            cpa16(bsb + (uint32_t)(br[p] * BSTR + bc) * 4u,
                  Bb + (size_t)(k0 + br[p]) * N + bc);
        cpa_commit();
    };

    float acc[2][8][4];
#pragma unroll
    for (int mi = 0; mi < 2; mi++)
#pragma unroll
        for (int ni = 0; ni < 8; ni++)
#pragma unroll
            for (int q = 0; q < 4; q++) acc[mi][ni][q] = 0.f;

    const int NIT = K / GBK;
    load_stage(0, 0);

    for (int it = 0; it < NIT; it++) {
        if (it + 1 < NIT) {
            load_stage((it + 1) & 1, (it + 1) * GBK);
            cpa_wait<1>();
        } else {
            cpa_wait<0>();
        }
        __syncthreads();

        const float* As = gsm + (it & 1) * STAGE_FLOATS;
        const float* Bs = As + GBM * ASTR;

#pragma unroll
        for (int ks = 0; ks < GBK / 8; ks++) {
            const int kk = ks * 8;
            uint32_t af[2][4];
#pragma unroll
            for (int mi = 0; mi < 2; mi++) {
                int r = wm + mi * 16 + g;
                af[mi][0] = __float_as_uint(As[r * ASTR + kk + t]);
                af[mi][1] = __float_as_uint(As[(r + 8) * ASTR + kk + t]);
                af[mi][2] = __float_as_uint(As[r * ASTR + kk + t + 4]);
                af[mi][3] = __float_as_uint(As[(r + 8) * ASTR + kk + t + 4]);
            }
            uint32_t bf[8][2];
#pragma unroll
            for (int ni = 0; ni < 8; ni++) {
                int c = wn + ni * 8 + g;
                bf[ni][0] = __float_as_uint(Bs[(kk + t) * BSTR + c]);
                bf[ni][1] = __float_as_uint(Bs[(kk + t + 4) * BSTR + c]);
            }
#pragma unroll
            for (int mi = 0; mi < 2; mi++)
#pragma unroll
                for (int ni = 0; ni < 8; ni++)
                    mma_tf32(acc[mi][ni], af[mi], bf[ni]);
        }
        __syncthreads();
    }

    const int row0 = blockIdx.y * GBM + wm;
    const int col0 = blockIdx.x * GBN + wn;
#pragma unroll
    for (int mi = 0; mi < 2; mi++) {
        int r = row0 + mi * 16 + g;
#pragma unroll
        for (int ni = 0; ni < 8; ni++) {
            int c = col0 + ni * 8 + t * 2;
            float b0 = 0.f, b1 = 0.f;
            if (bias) { b0 = bias[c]; b1 = bias[c + 1]; }
            float v0 = acc[mi][ni][0] + b0, v1 = acc[mi][ni][1] + b1;
            float v2 = acc[mi][ni][2] + b0, v3 = acc[mi][ni][3] + b1;
            if (round_out) {
                v0 = tf32r(v0); v1 = tf32r(v1);
                v2 = tf32r(v2); v3 = tf32r(v3);
            }
            *reinterpret_cast<float2*>(C + (size_t)r * N + c) =
                make_float2(v0, v1);
            *reinterpret_cast<float2*>(C + (size_t)(r + 8) * N + c) =
                make_float2(v2, v3);
        }
    }
}

// ---------------------------------------------------------------------------
// Flash attention with tf32 tensor cores. Q-tile 128, KV-tile 64, 8 warps.
// Inputs (g_qkv) are already tf32-rounded -> K/V/Q copied raw via cp.async.
// Scale 0.125 applied to hoisted Q fragments in registers (exact in tf32).
// ---------------------------------------------------------------------------
#define AQ_STR 68
#define AK_STR 68
#define AV_STR 72
#define BLKQ 128
#define ATTN_SMEM_FLOATS (BLKQ * AQ_STR + 64 * AK_STR + 64 * AV_STR)

__global__ void __launch_bounds__(256)
attn_mma_kernel(const float* __restrict__ qkv, float* __restrict__ out)
{
    extern __shared__ float sm[];
    float* sQP = sm;                         // 128 x 68 (Q, later P)
    float* sK  = sQP + BLKQ * AQ_STR;        // 64 x 68
    float* sV  = sK + 64 * AK_STR;           // 64 x 72

    const uint32_t sQPb = (uint32_t)__cvta_generic_to_shared(sQP);
    const uint32_t sKb  = (uint32_t)__cvta_generic_to_shared(sK);
    const uint32_t sVb  = (uint32_t)__cvta_generic_to_shared(sV);

    const int tid = threadIdx.x;
    const int lane = tid & 31;
    const int warp = tid >> 5;
    const int g = lane >> 2;
    const int t = lane & 3;
    const int m0 = warp * 16;

    const int qt = (int)(gridDim.x - 1) - (int)blockIdx.x;  // heavy first
    const int bh = blockIdx.y;
    const int b = bh >> 4, h = bh & 15;
    const float* base = qkv + (size_t)b * LSEQ * QKVN + h * HDIM;
    const int q0 = qt * BLKQ;

    // Load Q tile (128x64) raw via cp.async
#pragma unroll
    for (int p = 0; p < 8; p++) {
        int tt = tid + p * 256;
        int r = tt >> 4, c4 = (tt & 15) * 4;
        cpa16(sQPb + (uint32_t)(r * AQ_STR + c4) * 4u,
              base + (size_t)(q0 + r) * QKVN + c4);
    }
    cpa_commit();
    cpa_wait<0>();
    __syncthreads();

    // Hoist Q A-fragments, applying the 0.125 scale (power of 2: tf32-exact).
    uint32_t aq[8][4];
#pragma unroll
    for (int ks = 0; ks < 8; ks++) {
        int kk = ks * 8;
        aq[ks][0] = __float_as_uint(0.125f * sQP[(m0 + g) * AQ_STR + kk + t]);
        aq[ks][1] = __float_as_uint(0.125f * sQP[(m0 + 8 + g) * AQ_STR + kk + t]);
        aq[ks][2] = __float_as_uint(0.125f * sQP[(m0 + g) * AQ_STR + kk + t + 4]);
        aq[ks][3] = __float_as_uint(0.125f * sQP[(m0 + 8 + g) * AQ_STR + kk + t + 4]);
    }

    float o[8][4];
#pragma unroll
    for (int nt = 0; nt < 8; nt++)
#pragma unroll
        for (int q = 0; q < 4; q++) o[nt][q] = 0.f;
    float mr0 = -1e30f, mr1 = -1e30f, l0 = 0.f, l1 = 0.f;

    const int row0g = q0 + m0 + g;
    const int row1g = row0g + 8;
    const int nkv = 2 * qt + 2;

    for (int kt = 0; kt < nkv; kt++) {
        const int k0 = kt * 64;
        __syncthreads();  // previous iter's sK/sV reads complete

        // Load K,V tiles (64x64 each) raw via cp.async
#pragma unroll
        for (int p = 0; p < 4; p++) {
            int tt = tid + p * 256;
            int r = tt >> 4, c4 = (tt & 15) * 4;
            const float* rp = base + (size_t)(k0 + r) * QKVN + c4;
            cpa16(sKb + (uint32_t)(r * AK_STR + c4) * 4u, rp + DMODEL);
            cpa16(sVb + (uint32_t)(r * AV_STR + c4) * 4u, rp + 2 * DMODEL);
        }
        cpa_commit();
        cpa_wait<0>();
        __syncthreads();

        // S = (Q*scale) @ K^T : warp computes 16x64
        float s[8][4];
#pragma unroll
        for (int nt = 0; nt < 8; nt++)
#pragma unroll
            for (int q = 0; q < 4; q++) s[nt][q] = 0.f;

#pragma unroll
        for (int ks = 0; ks < 8; ks++) {
            const int kk = ks * 8;
#pragma unroll
            for (int nt = 0; nt < 8; nt++) {
                uint32_t bf[2];
                bf[0] = __float_as_uint(sK[(nt * 8 + g) * AK_STR + kk + t]);
                bf[1] = __float_as_uint(sK[(nt * 8 + g) * AK_STR + kk + t + 4]);
                mma_tf32(s[nt], aq[ks], bf);
            }
        }

        // Causal mask (only tiles touching the diagonal)
        if (kt >= 2 * qt) {
#pragma unroll
            for (int nt = 0; nt < 8; nt++) {
                int cb = k0 + nt * 8 + 2 * t;
#pragma unroll
                for (int q = 0; q < 2; q++) {
                    if (cb + q > row0g) s[nt][q] = -1e30f;
                    if (cb + q > row1g) s[nt][2 + q] = -1e30f;
                }
            }
        }

        // Online softmax (rows g and g+8; quad-reduce over t lanes)
        float mt0 = -1e30f, mt1 = -1e30f;
#pragma unroll
        for (int nt = 0; nt < 8; nt++) {
            mt0 = fmaxf(mt0, fmaxf(s[nt][0], s[nt][1]));
            mt1 = fmaxf(mt1, fmaxf(s[nt][2], s[nt][3]));
        }
        mt0 = fmaxf(mt0, __shfl_xor_sync(0xffffffffu, mt0, 1));
        mt0 = fmaxf(mt0, __shfl_xor_sync(0xffffffffu, mt0, 2));
        mt1 = fmaxf(mt1, __shfl_xor_sync(0xffffffffu, mt1, 1));
        mt1 = fmaxf(mt1, __shfl_xor_sync(0xffffffffu, mt1, 2));

        float mn0 = fmaxf(mr0, mt0), mn1 = fmaxf(mr1, mt1);
        float cr0 = __expf(mr0 - mn0), cr1 = __expf(mr1 - mn1);
        mr0 = mn0; mr1 = mn1;

        float rs0 = 0.f, rs1 = 0.f;
        float* p0row = &sQP[(m0 + g) * AQ_STR + 2 * t];
        float* p1row = &sQP[(m0 + 8 + g) * AQ_STR + 2 * t];
#pragma unroll
        for (int nt = 0; nt < 8; nt++) {
            float e0 = __expf(s[nt][0] - mn0);
            float e1 = __expf(s[nt][1] - mn0);
            float e2 = __expf(s[nt][2] - mn1);
            float e3 = __expf(s[nt][3] - mn1);
            rs0 += e0 + e1;
            rs1 += e2 + e3;
            p0row[nt * 8 + 0] = tf32r(e0);
            p0row[nt * 8 + 1] = tf32r(e1);
            p1row[nt * 8 + 0] = tf32r(e2);
            p1row[nt * 8 + 1] = tf32r(e3);
        }
        rs0 += __shfl_xor_sync(0xffffffffu, rs0, 1);
        rs0 += __shfl_xor_sync(0xffffffffu, rs0, 2);
        rs1 += __shfl_xor_sync(0xffffffffu, rs1, 1);
        rs1 += __shfl_xor_sync(0xffffffffu, rs1, 2);
        l0 = l0 * cr0 + rs0;
        l1 = l1 * cr1 + rs1;

#pragma unroll
        for (int nt = 0; nt < 8; nt++) {
            o[nt][0] *= cr0; o[nt][1] *= cr0;
            o[nt][2] *= cr1; o[nt][3] *= cr1;
        }
        __syncwarp();  // P stores visible to all lanes of this warp

        // O += P @ V
#pragma unroll
        for (int ks = 0; ks < 8; ks++) {
            const int kk = ks * 8;
            uint32_t ap[4];
            ap[0] = __float_as_uint(sQP[(m0 + g) * AQ_STR + kk + t]);
            ap[1] = __float_as_uint(sQP[(m0 + 8 + g) * AQ_STR + kk + t]);
            ap[2] = __float_as_uint(sQP[(m0 + g) * AQ_STR + kk + t + 4]);
            ap[3] = __float_as_uint(sQP[(m0 + 8 + g) * AQ_STR + kk + t + 4]);
#pragma unroll
            for (int nt = 0; nt < 8; nt++) {
                uint32_t bf[2];
                bf[0] = __float_as_uint(sV[(kk + t) * AV_STR + nt * 8 + g]);
                bf[1] = __float_as_uint(sV[(kk + t + 4) * AV_STR + nt * 8 + g]);
                mma_tf32(o[nt], ap, bf);
            }
        }
        __syncwarp();  // P reads done before next iter's P stores
    }

    // Epilogue: normalize, tf32-round (feeds proj GEMM), write (B*L, D)
    float inv0 = 1.0f / l0, inv1 = 1.0f / l1;
    float* ob0 = out + (size_t)(b * LSEQ + row0g) * DMODEL + h * HDIM + 2 * t;
    float* ob1 = out + (size_t)(b * LSEQ + row1g) * DMODEL + h * HDIM + 2 * t;
#pragma unroll
    for (int nt = 0; nt < 8; nt++) {
        *reinterpret_cast<float2*>(ob0 + nt * 8) =
            make_float2(tf32r(o[nt][0] * inv0), tf32r(o[nt][1] * inv0));
        *reinterpret_cast<float2*>(ob1 + nt * 8) =
            make_float2(tf32r(o[nt][2] * inv1), tf32r(o[nt][3] * inv1));
    }
}

// ---------------------------------------------------------------------------
extern "C" void kernel_launch(void* const* d_in, const int* in_sizes, int n_in,
                              void* d_out, int out_size)
{
    (void)in_sizes; (void)n_in; (void)out_size;
    const float* x      = (const float*)d_in[0];
    // d_in[1] = attn_mask (always causal triu(k=1); implemented directly)
    const float* w_qkv  = (const float*)d_in[2];
    const float* w_proj = (const float*)d_in[3];
    const float* b_proj = (const float*)d_in[4];
    float* out = (float*)d_out;

    float *qkv_p, *attn_p, *x_p, *wqkv_p, *wproj_p;
    cudaGetSymbolAddress((void**)&qkv_p, g_qkv);
    cudaGetSymbolAddress((void**)&attn_p, g_attn);
    cudaGetSymbolAddress((void**)&x_p, g_x);
    cudaGetSymbolAddress((void**)&wqkv_p, g_wqkv);
    cudaGetSymbolAddress((void**)&wproj_p, g_wproj);

    cudaFuncSetAttribute(gemm_tf32_kernel,
                         cudaFuncAttributeMaxDynamicSharedMemorySize,
                         GEMM_SMEM_BYTES);
    const int attn_smem = ATTN_SMEM_FLOATS * (int)sizeof(float);
    cudaFuncSetAttribute(attn_mma_kernel,
                         cudaFuncAttributeMaxDynamicSharedMemorySize,
                         attn_smem);

    // 0) Pre-round inputs to tf32 (hoists cvt off the GEMM hot path)
    {
        int n4x = MROWS * DMODEL / 4;
        round_tf32_kernel<<<(n4x + 255) / 256, 256>>>(
            (const float4*)x, (float4*)x_p, n4x);
        int n4w = DMODEL * QKVN / 4;
        round_tf32_kernel<<<(n4w + 255) / 256, 256>>>(
            (const float4*)w_qkv, (float4*)wqkv_p, n4w);
        int n4p = DMODEL * DMODEL / 4;
        round_tf32_kernel<<<(n4p + 255) / 256, 256>>>(
            (const float4*)w_proj, (float4*)wproj_p, n4p);
    }

    // 1) QKV GEMM: (8192,1024) @ (1024,3072), output tf32-rounded
    {
        dim3 grid(QKVN / GBN, MROWS / GBM);
        gemm_tf32_kernel<<<grid, 256, GEMM_SMEM_BYTES>>>(
            x_p, wqkv_p, qkv_p, MROWS, QKVN, DMODEL, nullptr, 1);
    }
    // 2) Causal flash attention [tf32 tensor cores]
    {
        dim3 grid(LSEQ / BLKQ, BB * NH);
        attn_mma_kernel<<<grid, 256, attn_smem>>>(qkv_p, attn_p);
    }
    // 3) Output projection + bias: (8192,1024) @ (1024,1024)
    {
        dim3 grid(DMODEL / GBN, MROWS / GBM);
        gemm_tf32_kernel<<<grid, 256, GEMM_SMEM_BYTES>>>(
            attn_p, wproj_p, out, MROWS, DMODEL, DMODEL, b_proj, 0);
    }
}

// round 9
// speedup vs baseline: 1.0973x; 1.0973x over previous
#include <cuda_runtime.h>
#include <cuda_bf16.h>
#include <cstddef>
#include <cstdint>
#include <math.h>

// Problem constants
#define BB 4
#define LSEQ 2048
#define DMODEL 1024
#define NH 16
#define HDIM 64
#define MROWS (BB * LSEQ)      // 8192
#define QKVN (3 * DMODEL)      // 3072

// Scratch (static device arrays; no allocation APIs allowed)
__device__ float g_qkv[(size_t)MROWS * QKVN];    // (B*L, 3D), tf32-rounded
__device__ float g_attn[(size_t)MROWS * DMODEL]; // (B*L, D), tf32-rounded
__device__ float g_x[(size_t)MROWS * DMODEL];    // x, tf32-rounded
__device__ float g_wqkv[(size_t)DMODEL * QKVN];  // w_qkv, tf32-rounded
__device__ float g_wproj[(size_t)DMODEL * DMODEL];

__device__ __forceinline__ float tf32r(float x) {
    float y;
    asm("cvt.rna.tf32.f32 %0, %1;" : "=f"(y) : "f"(x));
    return y;
}

__device__ __forceinline__ void mma_tf32(float* d, const uint32_t* a,
                                         const uint32_t* b) {
    asm volatile(
        "mma.sync.aligned.m16n8k8.row.col.f32.tf32.tf32.f32 "
        "{%0,%1,%2,%3}, {%4,%5,%6,%7}, {%8,%9}, {%0,%1,%2,%3};\n"
        : "+f"(d[0]), "+f"(d[1]), "+f"(d[2]), "+f"(d[3])
        : "r"(a[0]), "r"(a[1]), "r"(a[2]), "r"(a[3]), "r"(b[0]), "r"(b[1]));
}

__device__ __forceinline__ void cpa16(uint32_t dst_smem, const void* src) {
    asm volatile("cp.async.cg.shared.global [%0], [%1], 16;\n"
                 :: "r"(dst_smem), "l"(src));
}
__device__ __forceinline__ void cpa_commit() {
    asm volatile("cp.async.commit_group;\n");
}
template <int N>
__device__ __forceinline__ void cpa_wait() {
    asm volatile("cp.async.wait_group %0;\n" :: "n"(N));
}

// ---------------------------------------------------------------------------
// Elementwise tf32 pre-round (float4)
// ---------------------------------------------------------------------------
__global__ void round_tf32_kernel(const float4* __restrict__ in,
                                  float4* __restrict__ out, int n4)
{
    int i = blockIdx.x * blockDim.x + threadIdx.x;
    if (i < n4) {
        float4 v = in[i];
        v.x = tf32r(v.x); v.y = tf32r(v.y);
        v.z = tf32r(v.z); v.w = tf32r(v.w);
        out[i] = v;
    }
}

// ---------------------------------------------------------------------------
// TF32 tensor-core GEMM, 3-stage cp.async pipeline, one barrier per k-iter.
// C[M,N] = A[M,K] @ B[K,N] (+bias). Inputs already tf32-rounded.
// CTA tile 128x128x32, 8 warps (4 M x 2 N), warp tile 32x64.
// ---------------------------------------------------------------------------
#define GBM 128
#define GBN 128
#define GBK 32
#define ASTR 36
#define BSTR 136
#define NSTG 3
#define STAGE_FLOATS (GBM * ASTR + GBK * BSTR)
#define GEMM_SMEM_BYTES (NSTG * STAGE_FLOATS * (int)sizeof(float))

__global__ void __launch_bounds__(256, 2)
gemm_tf32_kernel(const float* __restrict__ A, const float* __restrict__ B,
                 float* __restrict__ C, int M, int N, int K,
                 const float* __restrict__ bias, int round_out)
{
    extern __shared__ float gsm[];

    const int tid = threadIdx.x;
    const int lane = tid & 31;
    const int warp = tid >> 5;
    const int wm = (warp & 3) * 32;
    const int wn = (warp >> 2) * 64;
    const int g = lane >> 2;
    const int t = lane & 3;

    const float* Ab = A + (size_t)blockIdx.y * GBM * K;
    const float* Bb = B + (size_t)blockIdx.x * GBN;

    const uint32_t smem0 = (uint32_t)__cvta_generic_to_shared(gsm);

    const int ar[4] = { (tid + 0) >> 3, (tid + 256) >> 3,
                        (tid + 512) >> 3, (tid + 768) >> 3 };
    const int ac = (tid & 7) * 4;
    const int br[4] = { (tid + 0) >> 5, (tid + 256) >> 5,
                        (tid + 512) >> 5, (tid + 768) >> 5 };
    const int bc = (tid & 31) * 4;

    auto load_stage = [&](int s, int k0) {
        uint32_t asb = smem0 + (uint32_t)(s * STAGE_FLOATS) * 4u;
        uint32_t bsb = asb + (uint32_t)(GBM * ASTR) * 4u;
#pragma unroll
        for (int p = 0; p < 4; p++)
            cpa16(asb + (uint32_t)(ar[p] * ASTR + ac) * 4u,
                  Ab + (size_t)ar[p] * K + k0 + ac);
#pragma unroll
        for (int p = 0; p < 4; p++)
            cpa16(bsb + (uint32_t)(br[p] * BSTR + bc) * 4u,
                  Bb + (size_t)(k0 + br[p]) * N + bc);
        cpa_commit();
    };

    float acc[2][8][4];
#pragma unroll
    for (int mi = 0; mi < 2; mi++)
#pragma unroll
        for (int ni = 0; ni < 8; ni++)
#pragma unroll
            for (int q = 0; q < 4; q++) acc[mi][ni][q] = 0.f;

    const int NIT = K / GBK;
    load_stage(0, 0);
    load_stage(1, GBK);

    int stg = 0;
    for (int it = 0; it < NIT; it++) {
        if (it + 1 < NIT) cpa_wait<1>(); else cpa_wait<0>();
        __syncthreads();  // stage `it` visible; all warps done with it-1

        if (it + 2 < NIT) load_stage((stg + 2) % NSTG, (it + 2) * GBK);

        const float* As = gsm + stg * STAGE_FLOATS;
        const float* Bs = As + GBM * ASTR;

#pragma unroll
        for (int ks = 0; ks < GBK / 8; ks++) {
            const int kk = ks * 8;
            uint32_t af[2][4];
#pragma unroll
            for (int mi = 0; mi < 2; mi++) {
                int r = wm + mi * 16 + g;
                af[mi][0] = __float_as_uint(As[r * ASTR + kk + t]);
                af[mi][1] = __float_as_uint(As[(r + 8) * ASTR + kk + t]);
                af[mi][2] = __float_as_uint(As[r * ASTR + kk + t + 4]);
                af[mi][3] = __float_as_uint(As[(r + 8) * ASTR + kk + t + 4]);
            }
            uint32_t bf[8][2];
#pragma unroll
            for (int ni = 0; ni < 8; ni++) {
                int c = wn + ni * 8 + g;
                bf[ni][0] = __float_as_uint(Bs[(kk + t) * BSTR + c]);
                bf[ni][1] = __float_as_uint(Bs[(kk + t + 4) * BSTR + c]);
            }
#pragma unroll
            for (int mi = 0; mi < 2; mi++)
#pragma unroll
                for (int ni = 0; ni < 8; ni++)
                    mma_tf32(acc[mi][ni], af[mi], bf[ni]);
        }
        stg = (stg + 1) % NSTG;
    }

    const int row0 = blockIdx.y * GBM + wm;
    const int col0 = blockIdx.x * GBN + wn;
#pragma unroll
    for (int mi = 0; mi < 2; mi++) {
        int r = row0 + mi * 16 + g;
#pragma unroll
        for (int ni = 0; ni < 8; ni++) {
            int c = col0 + ni * 8 + t * 2;
            float b0 = 0.f, b1 = 0.f;
            if (bias) { b0 = bias[c]; b1 = bias[c + 1]; }
            float v0 = acc[mi][ni][0] + b0, v1 = acc[mi][ni][1] + b1;
            float v2 = acc[mi][ni][2] + b0, v3 = acc[mi][ni][3] + b1;
            if (round_out) {
                v0 = tf32r(v0); v1 = tf32r(v1);
                v2 = tf32r(v2); v3 = tf32r(v3);
            }
            *reinterpret_cast<float2*>(C + (size_t)r * N + c) =
                make_float2(v0, v1);
            *reinterpret_cast<float2*>(C + (size_t)(r + 8) * N + c) =
                make_float2(v2, v3);
        }
    }
}

// ---------------------------------------------------------------------------
// Flash attention with tf32 tensor cores. Q-tile 128, KV-tile 64, 8 warps.
// K/V double-buffered via cp.async: tile kt+1 prefetches during compute of kt.
// ---------------------------------------------------------------------------
#define AQ_STR 68
#define AK_STR 68
#define AV_STR 72
#define BLKQ 128
#define KVST_FLOATS (64 * AK_STR + 64 * AV_STR)
#define ATTN_SMEM_FLOATS (BLKQ * AQ_STR + 2 * KVST_FLOATS)

__global__ void __launch_bounds__(256)
attn_mma_kernel(const float* __restrict__ qkv, float* __restrict__ out)
{
    extern __shared__ float sm[];
    float* sQP = sm;                           // 128 x 68 (Q, later P)
    float* sKV = sQP + BLKQ * AQ_STR;          // 2 stages of (K 64x68, V 64x72)

    const uint32_t sQPb = (uint32_t)__cvta_generic_to_shared(sQP);
    const uint32_t sKVb = (uint32_t)__cvta_generic_to_shared(sKV);

    const int tid = threadIdx.x;
    const int lane = tid & 31;
    const int warp = tid >> 5;
    const int g = lane >> 2;
    const int t = lane & 3;
    const int m0 = warp * 16;

    const int qt = (int)(gridDim.x - 1) - (int)blockIdx.x;  // heavy first
    const int bh = blockIdx.y;
    const int b = bh >> 4, h = bh & 15;
    const float* base = qkv + (size_t)b * LSEQ * QKVN + h * HDIM;
    const int q0 = qt * BLKQ;
    const int nkv = 2 * qt + 2;

    // copy coords for K/V loads (1024 float4 per tile pair, 4 per thread)
    const int kvr = tid >> 4;          // 0..15 base row
    const int kvc = (tid & 15) * 4;    // column (float)

    auto load_kv = [&](int kt, int stg) {
        uint32_t kb = sKVb + (uint32_t)(stg * KVST_FLOATS) * 4u;
        uint32_t vb = kb + (uint32_t)(64 * AK_STR) * 4u;
        const int k0 = kt * 64;
#pragma unroll
        for (int p = 0; p < 4; p++) {
            int r = kvr + p * 16;
            const float* rp = base + (size_t)(k0 + r) * QKVN + kvc;
            cpa16(kb + (uint32_t)(r * AK_STR + kvc) * 4u, rp + DMODEL);
            cpa16(vb + (uint32_t)(r * AV_STR + kvc) * 4u, rp + 2 * DMODEL);
        }
        cpa_commit();
    };

    // Issue Q load (group 0), then KV stage 0 (group 1)
#pragma unroll
    for (int p = 0; p < 8; p++) {
        int tt = tid + p * 256;
        int r = tt >> 4, c4 = (tt & 15) * 4;
        cpa16(sQPb + (uint32_t)(r * AQ_STR + c4) * 4u,
              base + (size_t)(q0 + r) * QKVN + c4);
    }
    cpa_commit();
    load_kv(0, 0);

    cpa_wait<1>();     // Q landed (KV0 may still be in flight)
    __syncthreads();

    // Hoist Q A-fragments, applying the 0.125 scale (power of 2: tf32-exact).
    uint32_t aq[8][4];
#pragma unroll
    for (int ks = 0; ks < 8; ks++) {
        int kk = ks * 8;
        aq[ks][0] = __float_as_uint(0.125f * sQP[(m0 + g) * AQ_STR + kk + t]);
        aq[ks][1] = __float_as_uint(0.125f * sQP[(m0 + 8 + g) * AQ_STR + kk + t]);
        aq[ks][2] = __float_as_uint(0.125f * sQP[(m0 + g) * AQ_STR + kk + t + 4]);
        aq[ks][3] = __float_as_uint(0.125f * sQP[(m0 + 8 + g) * AQ_STR + kk + t + 4]);
    }

    float o[8][4];
#pragma unroll
    for (int nt = 0; nt < 8; nt++)
#pragma unroll
        for (int q = 0; q < 4; q++) o[nt][q] = 0.f;
    float mr0 = -1e30f, mr1 = -1e30f, l0 = 0.f, l1 = 0.f;

    const int row0g = q0 + m0 + g;
    const int row1g = row0g + 8;

    for (int kt = 0; kt < nkv; kt++) {
        const int k0 = kt * 64;
        __syncthreads();  // all warps done reading stage (kt-1)&1

        if (kt + 1 < nkv) {
            load_kv(kt + 1, (kt + 1) & 1);
            cpa_wait<1>();     // stage kt ready; kt+1 in flight
        } else {
            cpa_wait<0>();
        }
        __syncthreads();

        const float* sK = sKV + (kt & 1) * KVST_FLOATS;
        const float* sV = sK + 64 * AK_STR;

        // S = (Q*scale) @ K^T : warp computes 16x64
        float s[8][4];
#pragma unroll
        for (int nt = 0; nt < 8; nt++)
#pragma unroll
            for (int q = 0; q < 4; q++) s[nt][q] = 0.f;

#pragma unroll
        for (int ks = 0; ks < 8; ks++) {
            const int kk = ks * 8;
#pragma unroll
            for (int nt = 0; nt < 8; nt++) {
                uint32_t bf[2];
                bf[0] = __float_as_uint(sK[(nt * 8 + g) * AK_STR + kk + t]);
                bf[1] = __float_as_uint(sK[(nt * 8 + g) * AK_STR + kk + t + 4]);
                mma_tf32(s[nt], aq[ks], bf);
            }
        }

        // Causal mask (only tiles touching the diagonal)
        if (kt >= 2 * qt) {
#pragma unroll
            for (int nt = 0; nt < 8; nt++) {
                int cb = k0 + nt * 8 + 2 * t;
#pragma unroll
                for (int q = 0; q < 2; q++) {
                    if (cb + q > row0g) s[nt][q] = -1e30f;
                    if (cb + q > row1g) s[nt][2 + q] = -1e30f;
                }
            }
        }

        // Online softmax (rows g and g+8; quad-reduce over t lanes)
        float mt0 = -1e30f, mt1 = -1e30f;
#pragma unroll
        for (int nt = 0; nt < 8; nt++) {
            mt0 = fmaxf(mt0, fmaxf(s[nt][0], s[nt][1]));
            mt1 = fmaxf(mt1, fmaxf(s[nt][2], s[nt][3]));
        }
        mt0 = fmaxf(mt0, __shfl_xor_sync(0xffffffffu, mt0, 1));
        mt0 = fmaxf(mt0, __shfl_xor_sync(0xffffffffu, mt0, 2));
        mt1 = fmaxf(mt1, __shfl_xor_sync(0xffffffffu, mt1, 1));
        mt1 = fmaxf(mt1, __shfl_xor_sync(0xffffffffu, mt1, 2));

        float mn0 = fmaxf(mr0, mt0), mn1 = fmaxf(mr1, mt1);
        float cr0 = __expf(mr0 - mn0), cr1 = __expf(mr1 - mn1);
        mr0 = mn0; mr1 = mn1;

        float rs0 = 0.f, rs1 = 0.f;
        float* p0row = &sQP[(m0 + g) * AQ_STR + 2 * t];
        float* p1row = &sQP[(m0 + 8 + g) * AQ_STR + 2 * t];
#pragma unroll
        for (int nt = 0; nt < 8; nt++) {
            float e0 = __expf(s[nt][0] - mn0);
            float e1 = __expf(s[nt][1] - mn0);
            float e2 = __expf(s[nt][2] - mn1);
            float e3 = __expf(s[nt][3] - mn1);
            rs0 += e0 + e1;
            rs1 += e2 + e3;
            p0row[nt * 8 + 0] = tf32r(e0);
            p0row[nt * 8 + 1] = tf32r(e1);
            p1row[nt * 8 + 0] = tf32r(e2);
            p1row[nt * 8 + 1] = tf32r(e3);
        }
        rs0 += __shfl_xor_sync(0xffffffffu, rs0, 1);
        rs0 += __shfl_xor_sync(0xffffffffu, rs0, 2);
        rs1 += __shfl_xor_sync(0xffffffffu, rs1, 1);
        rs1 += __shfl_xor_sync(0xffffffffu, rs1, 2);
        l0 = l0 * cr0 + rs0;
        l1 = l1 * cr1 + rs1;

#pragma unroll
        for (int nt = 0; nt < 8; nt++) {
            o[nt][0] *= cr0; o[nt][1] *= cr0;
            o[nt][2] *= cr1; o[nt][3] *= cr1;
        }
        __syncwarp();  // P stores visible within warp

        // O += P @ V
#pragma unroll
        for (int ks = 0; ks < 8; ks++) {
            const int kk = ks * 8;
            uint32_t ap[4];
            ap[0] = __float_as_uint(sQP[(m0 + g) * AQ_STR + kk + t]);
            ap[1] = __float_as_uint(sQP[(m0 + 8 + g) * AQ_STR + kk + t]);
            ap[2] = __float_as_uint(sQP[(m0 + g) * AQ_STR + kk + t + 4]);
            ap[3] = __float_as_uint(sQP[(m0 + 8 + g) * AQ_STR + kk + t + 4]);
#pragma unroll
            for (int nt = 0; nt < 8; nt++) {
                uint32_t bf[2];
                bf[0] = __float_as_uint(sV[(kk + t) * AV_STR + nt * 8 + g]);
                bf[1] = __float_as_uint(sV[(kk + t + 4) * AV_STR + nt * 8 + g]);
                mma_tf32(o[nt], ap, bf);
            }
        }
        __syncwarp();  // P reads done before next iter's P stores
    }

    // Epilogue: normalize, tf32-round (feeds proj GEMM), write (B*L, D)
    float inv0 = 1.0f / l0, inv1 = 1.0f / l1;
    float* ob0 = out + (size_t)(b * LSEQ + row0g) * DMODEL + h * HDIM + 2 * t;
    float* ob1 = out + (size_t)(b * LSEQ + row1g) * DMODEL + h * HDIM + 2 * t;
#pragma unroll
    for (int nt = 0; nt < 8; nt++) {
        *reinterpret_cast<float2*>(ob0 + nt * 8) =
            make_float2(tf32r(o[nt][0] * inv0), tf32r(o[nt][1] * inv0));
        *reinterpret_cast<float2*>(ob1 + nt * 8) =
            make_float2(tf32r(o[nt][2] * inv1), tf32r(o[nt][3] * inv1));
    }
}

// ---------------------------------------------------------------------------
extern "C" void kernel_launch(void* const* d_in, const int* in_sizes, int n_in,
                              void* d_out, int out_size)
{
    (void)in_sizes; (void)n_in; (void)out_size;
    const float* x      = (const float*)d_in[0];
    // d_in[1] = attn_mask (always causal triu(k=1); implemented directly)
    const float* w_qkv  = (const float*)d_in[2];
    const float* w_proj = (const float*)d_in[3];
    const float* b_proj = (const float*)d_in[4];
    float* out = (float*)d_out;

    float *qkv_p, *attn_p, *x_p, *wqkv_p, *wproj_p;
    cudaGetSymbolAddress((void**)&qkv_p, g_qkv);
    cudaGetSymbolAddress((void**)&attn_p, g_attn);
    cudaGetSymbolAddress((void**)&x_p, g_x);
    cudaGetSymbolAddress((void**)&wqkv_p, g_wqkv);
    cudaGetSymbolAddress((void**)&wproj_p, g_wproj);

    cudaFuncSetAttribute(gemm_tf32_kernel,
                         cudaFuncAttributeMaxDynamicSharedMemorySize,
                         GEMM_SMEM_BYTES);
    const int attn_smem = ATTN_SMEM_FLOATS * (int)sizeof(float);
    cudaFuncSetAttribute(attn_mma_kernel,
                         cudaFuncAttributeMaxDynamicSharedMemorySize,
                         attn_smem);

    // 0) Pre-round inputs to tf32
    {
        int n4x = MROWS * DMODEL / 4;
        round_tf32_kernel<<<(n4x + 255) / 256, 256>>>(
            (const float4*)x, (float4*)x_p, n4x);
        int n4w = DMODEL * QKVN / 4;
        round_tf32_kernel<<<(n4w + 255) / 256, 256>>>(
            (const float4*)w_qkv, (float4*)wqkv_p, n4w);
        int n4p = DMODEL * DMODEL / 4;
        round_tf32_kernel<<<(n4p + 255) / 256, 256>>>(
            (const float4*)w_proj, (float4*)wproj_p, n4p);
    }

    // 1) QKV GEMM: (8192,1024) @ (1024,3072), output tf32-rounded
    {
        dim3 grid(QKVN / GBN, MROWS / GBM);
        gemm_tf32_kernel<<<grid, 256, GEMM_SMEM_BYTES>>>(
            x_p, wqkv_p, qkv_p, MROWS, QKVN, DMODEL, nullptr, 1);
    }
    // 2) Causal flash attention [tf32, double-buffered K/V]
    {
        dim3 grid(LSEQ / BLKQ, BB * NH);
        attn_mma_kernel<<<grid, 256, attn_smem>>>(qkv_p, attn_p);
    }
    // 3) Output projection + bias: (8192,1024) @ (1024,1024)
    {
        dim3 grid(DMODEL / GBN, MROWS / GBM);
        gemm_tf32_kernel<<<grid, 256, GEMM_SMEM_BYTES>>>(
            attn_p, wproj_p, out, MROWS, DMODEL, DMODEL, b_proj, 0);
    }
}

// round 11
// speedup vs baseline: 1.8867x; 1.7194x over previous
#include <cuda_runtime.h>
#include <cuda_fp16.h>
#include <cstddef>
#include <cstdint>
#include <math.h>

// Problem constants
#define BB 4
#define LSEQ 2048
#define DMODEL 1024
#define NH 16
#define HDIM 64
#define MROWS (BB * LSEQ)      // 8192
#define QKVN (3 * DMODEL)      // 3072

// Scratch (static device arrays; no allocation APIs allowed)
__device__ __half g_x_h[(size_t)MROWS * DMODEL];
__device__ __half g_wqkvT_h[(size_t)QKVN * DMODEL];   // (3072,1024) K-major
__device__ __half g_wprojT_h[(size_t)DMODEL * DMODEL];
__device__ __half g_qkv_h[(size_t)MROWS * QKVN];
__device__ __half g_attn_h[(size_t)MROWS * DMODEL];

// ---- fp16 MMA m16n8k16, fp32 accumulate ----------------------------------
__device__ __forceinline__ void mma_f16(float* d, const uint32_t* a,
                                        const uint32_t* b) {
    asm volatile(
        "mma.sync.aligned.m16n8k16.row.col.f32.f16.f16.f32 "
        "{%0,%1,%2,%3}, {%4,%5,%6,%7}, {%8,%9}, {%0,%1,%2,%3};\n"
        : "+f"(d[0]), "+f"(d[1]), "+f"(d[2]), "+f"(d[3])
        : "r"(a[0]), "r"(a[1]), "r"(a[2]), "r"(a[3]), "r"(b[0]), "r"(b[1]));
}

__device__ __forceinline__ void ldsm_x4_t(uint32_t* r, uint32_t addr) {
    asm volatile(
        "ldmatrix.sync.aligned.m8n8.x4.trans.shared.b16 {%0,%1,%2,%3}, [%4];"
        : "=r"(r[0]), "=r"(r[1]), "=r"(r[2]), "=r"(r[3]) : "r"(addr));
}

__device__ __forceinline__ void cpa16(uint32_t dst_smem, const void* src) {
    asm volatile("cp.async.cg.shared.global [%0], [%1], 16;\n"
                 :: "r"(dst_smem), "l"(src));
}
__device__ __forceinline__ void cpa_commit() {
    asm volatile("cp.async.commit_group;\n");
}
template <int N>
__device__ __forceinline__ void cpa_wait() {
    asm volatile("cp.async.wait_group %0;\n" :: "n"(N));
}
__device__ __forceinline__ uint32_t smem_u32(const void* p) {
    return (uint32_t)__cvta_generic_to_shared(p);
}
__device__ __forceinline__ uint32_t ldh2(const __half* p) {
    return *reinterpret_cast<const uint32_t*>(p);
}
__device__ __forceinline__ uint32_t packh2(float lo, float hi) {
    __half2 h = __floats2half2_rn(lo, hi);
    return *reinterpret_cast<uint32_t*>(&h);
}

// ---------------------------------------------------------------------------
// Pre-pass kernels: fp32 -> fp16 convert / transpose
// ---------------------------------------------------------------------------
__global__ void f2h_kernel(const float4* __restrict__ in,
                           uint2* __restrict__ out, int n4)
{
    int i = blockIdx.x * blockDim.x + threadIdx.x;
    if (i < n4) {
        float4 v = in[i];
        out[i] = make_uint2(packh2(v.x, v.y), packh2(v.z, v.w));
    }
}

// in (R, C) fp32 -> out (C, R) fp16
__global__ void transpose_h_kernel(const float* __restrict__ in,
                                   __half* __restrict__ out, int R, int C)
{
    __shared__ float tile[32][33];
    int gx = blockIdx.x * 32, gy = blockIdx.y * 32;
    int tx = threadIdx.x, ty = threadIdx.y;
#pragma unroll
    for (int j = 0; j < 4; j++)
        tile[ty + j * 8][tx] = in[(size_t)(gy + ty + j * 8) * C + gx + tx];
    __syncthreads();
#pragma unroll
    for (int j = 0; j < 4; j++)
        out[(size_t)(gx + ty + j * 8) * R + gy + tx] =
            __float2half(tile[tx][ty + j * 8]);
}

// ---------------------------------------------------------------------------
// fp16 tensor-core GEMM: C[M,N] = A[M,K] @ BT[N,K]^T (+bias).
// CTA tile 128x128, BK=32 halves, 8 warps (4M x 2N), warp tile 32x64.
// mma.m16n8k16. A [M][K] stride 40 halves (80B), BT [N][K] stride 40.
// Fragment gather bank = (g*20 + t) mod 32 -> conflict-free.
// 3-stage cp.async pipeline.
// ---------------------------------------------------------------------------
#define HSTR 40
#define GNSTG 3
#define GSTAGE_BYTES (256 * HSTR * 2)   // 20480
#define GEMM_SMEM_BYTES (GNSTG * GSTAGE_BYTES)

__global__ void __launch_bounds__(256, 2)
gemm_f16_kernel(const __half* __restrict__ A, const __half* __restrict__ BT,
                float* __restrict__ Cf, __half* __restrict__ Ch,
                int M, int N, int K, const float* __restrict__ bias)
{
    extern __shared__ char gsm[];
    const uint32_t smb = smem_u32(gsm);

    const int tid = threadIdx.x;
    const int lane = tid & 31;
    const int warp = tid >> 5;
    const int wm = (warp & 3) * 32;
    const int wn = (warp >> 2) * 64;
    const int g = lane >> 2;
    const int t = lane & 3;

    const __half* Ab  = A  + (size_t)blockIdx.y * 128 * K;
    const __half* BTb = BT + (size_t)blockIdx.x * 128 * K;

    auto load_stage = [&](int s, int k0) {
        uint32_t sa = smb + (uint32_t)(s * GSTAGE_BYTES);
        uint32_t sb = sa + 128u * 80u;
#pragma unroll
        for (int p = 0; p < 2; p++) {
            int idx = tid + p * 256;
            int r = idx >> 2, c16 = idx & 3;
            cpa16(sa + (uint32_t)(r * 80 + c16 * 16),
                  Ab + (size_t)r * K + k0 + c16 * 8);
        }
#pragma unroll
        for (int p = 0; p < 2; p++) {
            int idx = tid + p * 256;
            int r = idx >> 2, c16 = idx & 3;
            cpa16(sb + (uint32_t)(r * 80 + c16 * 16),
                  BTb + (size_t)r * K + k0 + c16 * 8);
        }
        cpa_commit();
    };

    float acc[2][8][4];
#pragma unroll
    for (int mi = 0; mi < 2; mi++)
#pragma unroll
        for (int ni = 0; ni < 8; ni++)
#pragma unroll
            for (int q = 0; q < 4; q++) acc[mi][ni][q] = 0.f;

    const int NIT = K / 32;
    load_stage(0, 0);
    load_stage(1, 32);

    int stg = 0;
    for (int it = 0; it < NIT; it++) {
        if (it + 1 < NIT) cpa_wait<1>(); else cpa_wait<0>();
        __syncthreads();
        if (it + 2 < NIT) load_stage((stg + 2) % GNSTG, (it + 2) * 32);

        const __half* As = (const __half*)(gsm + stg * GSTAGE_BYTES);
        const __half* Bs = As + 128 * HSTR;

#pragma unroll
        for (int ks = 0; ks < 2; ks++) {
            const int kh = ks * 16;
            uint32_t af[2][4];
#pragma unroll
            for (int mi = 0; mi < 2; mi++) {
                const __half* r0 = As + (wm + mi * 16 + g) * HSTR + kh + 2 * t;
                const __half* r1 = r0 + 8 * HSTR;
                af[mi][0] = ldh2(r0);
                af[mi][1] = ldh2(r1);
                af[mi][2] = ldh2(r0 + 8);
                af[mi][3] = ldh2(r1 + 8);
            }
            uint32_t bf[8][2];
#pragma unroll
            for (int ni = 0; ni < 8; ni++) {
                const __half* rb = Bs + (wn + ni * 8 + g) * HSTR + kh + 2 * t;
                bf[ni][0] = ldh2(rb);
                bf[ni][1] = ldh2(rb + 8);
            }
#pragma unroll
            for (int mi = 0; mi < 2; mi++)
#pragma unroll
                for (int ni = 0; ni < 8; ni++)
                    mma_f16(acc[mi][ni], af[mi], bf[ni]);
        }
        stg = (stg + 1) % GNSTG;
    }

    const int row0 = blockIdx.y * 128 + wm;
    const int col0 = blockIdx.x * 128 + wn;
#pragma unroll
    for (int mi = 0; mi < 2; mi++) {
        int r = row0 + mi * 16 + g;
#pragma unroll
        for (int ni = 0; ni < 8; ni++) {
            int c = col0 + ni * 8 + t * 2;
            if (Ch) {
                *reinterpret_cast<uint32_t*>(Ch + (size_t)r * N + c) =
                    packh2(acc[mi][ni][0], acc[mi][ni][1]);
                *reinterpret_cast<uint32_t*>(Ch + (size_t)(r + 8) * N + c) =
                    packh2(acc[mi][ni][2], acc[mi][ni][3]);
            } else {
                float b0 = 0.f, b1 = 0.f;
                if (bias) { b0 = bias[c]; b1 = bias[c + 1]; }
                *reinterpret_cast<float2*>(Cf + (size_t)r * N + c) =
                    make_float2(acc[mi][ni][0] + b0, acc[mi][ni][1] + b1);
                *reinterpret_cast<float2*>(Cf + (size_t)(r + 8) * N + c) =
                    make_float2(acc[mi][ni][2] + b0, acc[mi][ni][3] + b1);
            }
        }
    }
}

// ---------------------------------------------------------------------------
// fp16 flash attention. Q-tile 128, KV-tile 64, 8 warps (16 Q rows each).
// P is register-resident (S output frag == A input frag layout for m16n8k16).
// V fragments via ldmatrix.x4.trans. K/V double-buffered cp.async.
// Smem (halves): sQ 128x72, then 2 stages of (K 64x72, V 64x72).
// ---------------------------------------------------------------------------
#define ASTRH 72
#define BLKQ 128
#define KVSTG_BYTES (2 * 64 * ASTRH * 2)   // K+V per stage = 18432
#define ATTN_SMEM_BYTES (BLKQ * ASTRH * 2 + 2 * KVSTG_BYTES)

__global__ void __launch_bounds__(256)
attn_f16_kernel(const __half* __restrict__ qkv, __half* __restrict__ out)
{
    extern __shared__ char asm_[];
    __half* sQ = (__half*)asm_;
    const uint32_t sQb  = smem_u32(sQ);
    const uint32_t sKVb = sQb + BLKQ * ASTRH * 2;

    const int tid = threadIdx.x;
    const int lane = tid & 31;
    const int warp = tid >> 5;
    const int g = lane >> 2;
    const int t = lane & 3;
    const int m0 = warp * 16;

    const int qt = (int)(gridDim.x - 1) - (int)blockIdx.x;  // heavy first
    const int bh = blockIdx.y;
    const int b = bh >> 4, h = bh & 15;
    const __half* base = qkv + (size_t)b * LSEQ * QKVN + h * HDIM;
    const int q0 = qt * BLKQ;
    const int nkv = 2 * qt + 2;

    auto load_kv = [&](int kt, int stg) {
        uint32_t kb = sKVb + (uint32_t)(stg * KVSTG_BYTES);
        uint32_t vb = kb + 64u * ASTRH * 2u;
        const int k0 = kt * 64;
#pragma unroll
        for (int p = 0; p < 2; p++) {
            int idx = tid + p * 256;
            int r = idx >> 3, c16 = idx & 7;
            const __half* rp = base + (size_t)(k0 + r) * QKVN + c16 * 8;
            cpa16(kb + (uint32_t)(r * 144 + c16 * 16), rp + DMODEL);
            cpa16(vb + (uint32_t)(r * 144 + c16 * 16), rp + 2 * DMODEL);
        }
        cpa_commit();
    };

    // Q load (own group), then KV stage 0
#pragma unroll
    for (int p = 0; p < 4; p++) {
        int idx = tid + p * 256;
        int r = idx >> 3, c16 = idx & 7;
        cpa16(sQb + (uint32_t)(r * 144 + c16 * 16),
              base + (size_t)(q0 + r) * QKVN + c16 * 8);
    }
    cpa_commit();
    load_kv(0, 0);

    cpa_wait<1>();   // Q landed
    __syncthreads();

    // Hoist Q fragments, scaled by 0.125 (power of 2: exact in fp16)
    const __half2 sc = __float2half2_rn(0.125f);
    uint32_t aq[4][4];
#pragma unroll
    for (int ks = 0; ks < 4; ks++) {
        const __half* r0 = sQ + (m0 + g) * ASTRH + ks * 16 + 2 * t;
        const __half* r1 = r0 + 8 * ASTRH;
        __half2 v0 = __hmul2(*(const __half2*)r0, sc);
        __half2 v1 = __hmul2(*(const __half2*)r1, sc);
        __half2 v2 = __hmul2(*(const __half2*)(r0 + 8), sc);
        __half2 v3 = __hmul2(*(const __half2*)(r1 + 8), sc);
        aq[ks][0] = *reinterpret_cast<uint32_t*>(&v0);
        aq[ks][1] = *reinterpret_cast<uint32_t*>(&v1);
        aq[ks][2] = *reinterpret_cast<uint32_t*>(&v2);
        aq[ks][3] = *reinterpret_cast<uint32_t*>(&v3);
    }

    float o[8][4];
#pragma unroll
    for (int nt = 0; nt < 8; nt++)
#pragma unroll
        for (int q = 0; q < 4; q++) o[nt][q] = 0.f;
    float mr0 = -1e30f, mr1 = -1e30f, l0 = 0.f, l1 = 0.f;

    const int row0g = q0 + m0 + g;
    const int row1g = row0g + 8;

    for (int kt = 0; kt < nkv; kt++) {
        const int k0 = kt * 64;
        __syncthreads();   // all warps done reading previous stage

        if (kt + 1 < nkv) {
            load_kv(kt + 1, (kt + 1) & 1);
            cpa_wait<1>();
        } else {
            cpa_wait<0>();
        }
        __syncthreads();

        const uint32_t kvb = sKVb + (uint32_t)((kt & 1) * KVSTG_BYTES);
        const __half* sK = (const __half*)(asm_ + (kvb - sQb));
        const uint32_t sVb = kvb + 64u * ASTRH * 2u;

        // S = (Q*scale) @ K^T : 16x64 per warp, 32 MMAs
        float s[8][4];
#pragma unroll
        for (int nt = 0; nt < 8; nt++)
#pragma unroll
            for (int q = 0; q < 4; q++) s[nt][q] = 0.f;

#pragma unroll
        for (int ks = 0; ks < 4; ks++) {
            const int kh = ks * 16;
#pragma unroll
            for (int nt = 0; nt < 8; nt++) {
                const __half* rb = sK + (nt * 8 + g) * ASTRH + kh + 2 * t;
                uint32_t bf[2];
                bf[0] = ldh2(rb);
                bf[1] = ldh2(rb + 8);
                mma_f16(s[nt], aq[ks], bf);
            }
        }

        // Causal mask (diagonal tiles only)
        if (kt >= 2 * qt) {
#pragma unroll
            for (int nt = 0; nt < 8; nt++) {
                int cb = k0 + nt * 8 + 2 * t;
#pragma unroll
                for (int q = 0; q < 2; q++) {
                    if (cb + q > row0g) s[nt][q] = -1e30f;
                    if (cb + q > row1g) s[nt][2 + q] = -1e30f;
                }
            }
        }

        // Online softmax (rows g and g+8; quad-reduce over t lanes)
        float mt0 = -1e30f, mt1 = -1e30f;
#pragma unroll
        for (int nt = 0; nt < 8; nt++) {
            mt0 = fmaxf(mt0, fmaxf(s[nt][0], s[nt][1]));
            mt1 = fmaxf(mt1, fmaxf(s[nt][2], s[nt][3]));
        }
        mt0 = fmaxf(mt0, __shfl_xor_sync(0xffffffffu, mt0, 1));
        mt0 = fmaxf(mt0, __shfl_xor_sync(0xffffffffu, mt0, 2));
        mt1 = fmaxf(mt1, __shfl_xor_sync(0xffffffffu, mt1, 1));
        mt1 = fmaxf(mt1, __shfl_xor_sync(0xffffffffu, mt1, 2));

        float mn0 = fmaxf(mr0, mt0), mn1 = fmaxf(mr1, mt1);
        float cr0 = __expf(mr0 - mn0), cr1 = __expf(mr1 - mn1);
        mr0 = mn0; mr1 = mn1;

        float rs0 = 0.f, rs1 = 0.f;
#pragma unroll
        for (int nt = 0; nt < 8; nt++) {
            s[nt][0] = __expf(s[nt][0] - mn0);
            s[nt][1] = __expf(s[nt][1] - mn0);
            s[nt][2] = __expf(s[nt][2] - mn1);
            s[nt][3] = __expf(s[nt][3] - mn1);
            rs0 += s[nt][0] + s[nt][1];
            rs1 += s[nt][2] + s[nt][3];
        }
        rs0 += __shfl_xor_sync(0xffffffffu, rs0, 1);
        rs0 += __shfl_xor_sync(0xffffffffu, rs0, 2);
        rs1 += __shfl_xor_sync(0xffffffffu, rs1, 1);
        rs1 += __shfl_xor_sync(0xffffffffu, rs1, 2);
        l0 = l0 * cr0 + rs0;
        l1 = l1 * cr1 + rs1;

#pragma unroll
        for (int nt = 0; nt < 8; nt++) {
            o[nt][0] *= cr0; o[nt][1] *= cr0;
            o[nt][2] *= cr1; o[nt][3] *= cr1;
        }

        // Pack P fragments in registers: ap[ks] covers kv cols 16ks..16ks+15
        uint32_t ap[4][4];
#pragma unroll
        for (int ks = 0; ks < 4; ks++) {
            ap[ks][0] = packh2(s[2 * ks][0], s[2 * ks][1]);
            ap[ks][1] = packh2(s[2 * ks][2], s[2 * ks][3]);
            ap[ks][2] = packh2(s[2 * ks + 1][0], s[2 * ks + 1][1]);
            ap[ks][3] = packh2(s[2 * ks + 1][2], s[2 * ks + 1][3]);
        }

        // O += P @ V, V frags via ldmatrix.x4.trans
#pragma unroll
        for (int ks = 0; ks < 4; ks++) {
#pragma unroll
            for (int ntp = 0; ntp < 4; ntp++) {
                uint32_t bv[4];
                uint32_t vaddr = sVb +
                    (uint32_t)(((16 * ks + (lane & 15)) * ASTRH +
                                ntp * 16 + ((lane >> 4) << 3)) * 2);
                ldsm_x4_t(bv, vaddr);
                mma_f16(o[2 * ntp],     ap[ks], bv);
                mma_f16(o[2 * ntp + 1], ap[ks], bv + 2);
            }
        }
    }

    // Epilogue: normalize, write fp16 (B*L, D)
    float inv0 = 1.0f / l0, inv1 = 1.0f / l1;
    __half* ob0 = out + (size_t)(b * LSEQ + row0g) * DMODEL + h * HDIM + 2 * t;
    __half* ob1 = out + (size_t)(b * LSEQ + row1g) * DMODEL + h * HDIM + 2 * t;
#pragma unroll
    for (int nt = 0; nt < 8; nt++) {
        *reinterpret_cast<uint32_t*>(ob0 + nt * 8) =
            packh2(o[nt][0] * inv0, o[nt][1] * inv0);
        *reinterpret_cast<uint32_t*>(ob1 + nt * 8) =
            packh2(o[nt][2] * inv1, o[nt][3] * inv1);
    }
}

// ---------------------------------------------------------------------------
extern "C" void kernel_launch(void* const* d_in, const int* in_sizes, int n_in,
                              void* d_out, int out_size)
{
    (void)in_sizes; (void)n_in; (void)out_size;
    const float* x      = (const float*)d_in[0];
    // d_in[1] = attn_mask (always causal triu(k=1); implemented directly)
    const float* w_qkv  = (const float*)d_in[2];
    const float* w_proj = (const float*)d_in[3];
    const float* b_proj = (const float*)d_in[4];
    float* out = (float*)d_out;

    __half *xh, *wqkvT, *wprojT, *qkvh, *attnh;
    cudaGetSymbolAddress((void**)&xh, g_x_h);
    cudaGetSymbolAddress((void**)&wqkvT, g_wqkvT_h);
    cudaGetSymbolAddress((void**)&wprojT, g_wprojT_h);
    cudaGetSymbolAddress((void**)&qkvh, g_qkv_h);
    cudaGetSymbolAddress((void**)&attnh, g_attn_h);

    cudaFuncSetAttribute(gemm_f16_kernel,
                         cudaFuncAttributeMaxDynamicSharedMemorySize,
                         GEMM_SMEM_BYTES);
    cudaFuncSetAttribute(attn_f16_kernel,
                         cudaFuncAttributeMaxDynamicSharedMemorySize,
                         ATTN_SMEM_BYTES);

    // 0) Pre-pass: fp16 convert x; transpose+convert weights to [N][K]
    {
        int n4x = MROWS * DMODEL / 4;
        f2h_kernel<<<(n4x + 255) / 256, 256>>>(
            (const float4*)x, (uint2*)xh, n4x);
        dim3 tb(32, 8);
        transpose_h_kernel<<<dim3(QKVN / 32, DMODEL / 32), tb>>>(
            w_qkv, wqkvT, DMODEL, QKVN);
        transpose_h_kernel<<<dim3(DMODEL / 32, DMODEL / 32), tb>>>(
            w_proj, wprojT, DMODEL, DMODEL);
    }

    // 1) QKV GEMM: (8192,1024) @ (1024,3072), fp16 out
    {
        dim3 grid(QKVN / 128, MROWS / 128);
        gemm_f16_kernel<<<grid, 256, GEMM_SMEM_BYTES>>>(
            xh, wqkvT, nullptr, qkvh, MROWS, QKVN, DMODEL, nullptr);
    }
    // 2) Causal flash attention (fp16 MMA, register P, ldmatrix V)
    {
        dim3 grid(LSEQ / BLKQ, BB * NH);
        attn_f16_kernel<<<grid, 256, ATTN_SMEM_BYTES>>>(qkvh, attnh);
    }
    // 3) Output projection + bias: (8192,1024) @ (1024,1024), fp32 out
    {
        dim3 grid(DMODEL / 128, MROWS / 128);
        gemm_f16_kernel<<<grid, 256, GEMM_SMEM_BYTES>>>(
            attnh, wprojT, out, nullptr, MROWS, DMODEL, DMODEL, b_proj);
    }
}

// round 12
// speedup vs baseline: 2.0381x; 1.0803x over previous
#include <cuda_runtime.h>
#include <cuda_fp16.h>
#include <cstddef>
#include <cstdint>
#include <math.h>

// Problem constants
#define BB 4
#define LSEQ 2048
#define DMODEL 1024
#define NH 16
#define HDIM 64
#define MROWS (BB * LSEQ)      // 8192
#define QKVN (3 * DMODEL)      // 3072

// Scratch (static device arrays; no allocation APIs allowed)
__device__ __half g_x_h[(size_t)MROWS * DMODEL];
__device__ __half g_wqkvT_h[(size_t)QKVN * DMODEL];   // (3072,1024) K-major
__device__ __half g_wprojT_h[(size_t)DMODEL * DMODEL];
__device__ __half g_qkv_h[(size_t)MROWS * QKVN];
__device__ __half g_attn_h[(size_t)MROWS * DMODEL];

// ---- fp16 MMA m16n8k16, fp32 accumulate ----------------------------------
__device__ __forceinline__ void mma_f16(float* d, const uint32_t* a,
                                        const uint32_t* b) {
    asm volatile(
        "mma.sync.aligned.m16n8k16.row.col.f32.f16.f16.f32 "
        "{%0,%1,%2,%3}, {%4,%5,%6,%7}, {%8,%9}, {%0,%1,%2,%3};\n"
        : "+f"(d[0]), "+f"(d[1]), "+f"(d[2]), "+f"(d[3])
        : "r"(a[0]), "r"(a[1]), "r"(a[2]), "r"(a[3]), "r"(b[0]), "r"(b[1]));
}

__device__ __forceinline__ void ldsm_x4(uint32_t* r, uint32_t addr) {
    asm volatile(
        "ldmatrix.sync.aligned.m8n8.x4.shared.b16 {%0,%1,%2,%3}, [%4];"
        : "=r"(r[0]), "=r"(r[1]), "=r"(r[2]), "=r"(r[3]) : "r"(addr));
}
__device__ __forceinline__ void ldsm_x4_t(uint32_t* r, uint32_t addr) {
    asm volatile(
        "ldmatrix.sync.aligned.m8n8.x4.trans.shared.b16 {%0,%1,%2,%3}, [%4];"
        : "=r"(r[0]), "=r"(r[1]), "=r"(r[2]), "=r"(r[3]) : "r"(addr));
}

__device__ __forceinline__ void cpa16(uint32_t dst_smem, const void* src) {
    asm volatile("cp.async.cg.shared.global [%0], [%1], 16;\n"
                 :: "r"(dst_smem), "l"(src));
}
__device__ __forceinline__ void cpa_commit() {
    asm volatile("cp.async.commit_group;\n");
}
template <int N>
__device__ __forceinline__ void cpa_wait() {
    asm volatile("cp.async.wait_group %0;\n" :: "n"(N));
}
__device__ __forceinline__ uint32_t smem_u32(const void* p) {
    return (uint32_t)__cvta_generic_to_shared(p);
}
__device__ __forceinline__ uint32_t packh2(float lo, float hi) {
    __half2 h = __floats2half2_rn(lo, hi);
    return *reinterpret_cast<uint32_t*>(&h);
}

// ---------------------------------------------------------------------------
// Pre-pass kernels: fp32 -> fp16 convert / transpose
// ---------------------------------------------------------------------------
__global__ void f2h_kernel(const float4* __restrict__ in,
                           uint2* __restrict__ out, int n4)
{
    int i = blockIdx.x * blockDim.x + threadIdx.x;
    if (i < n4) {
        float4 v = in[i];
        out[i] = make_uint2(packh2(v.x, v.y), packh2(v.z, v.w));
    }
}

// in (R, C) fp32 -> out (C, R) fp16
__global__ void transpose_h_kernel(const float* __restrict__ in,
                                   __half* __restrict__ out, int R, int C)
{
    __shared__ float tile[32][33];
    int gx = blockIdx.x * 32, gy = blockIdx.y * 32;
    int tx = threadIdx.x, ty = threadIdx.y;
#pragma unroll
    for (int j = 0; j < 4; j++)
        tile[ty + j * 8][tx] = in[(size_t)(gy + ty + j * 8) * C + gx + tx];
    __syncthreads();
#pragma unroll
    for (int j = 0; j < 4; j++)
        out[(size_t)(gx + ty + j * 8) * R + gy + tx] =
            __float2half(tile[tx][ty + j * 8]);
}

// ---------------------------------------------------------------------------
// fp16 tensor-core GEMM: C[M,N] = A[M,K] @ BT[N,K]^T (+bias).
// CTA tile 128x128, BK=32 halves, 8 warps (4M x 2N), warp tile 32x64.
// All fragments via ldmatrix.x4 (80B row stride -> conflict-free phases).
// 3-stage cp.async pipeline.
// ---------------------------------------------------------------------------
#define HSTR 40
#define GNSTG 3
#define GSTAGE_BYTES (256 * HSTR * 2)   // 20480
#define GEMM_SMEM_BYTES (GNSTG * GSTAGE_BYTES)

__global__ void __launch_bounds__(256, 2)
gemm_f16_kernel(const __half* __restrict__ A, const __half* __restrict__ BT,
                float* __restrict__ Cf, __half* __restrict__ Ch,
                int M, int N, int K, const float* __restrict__ bias)
{
    extern __shared__ char gsm[];
    const uint32_t smb = smem_u32(gsm);

    const int tid = threadIdx.x;
    const int lane = tid & 31;
    const int warp = tid >> 5;
    const int wm = (warp & 3) * 32;
    const int wn = (warp >> 2) * 64;
    const int g = lane >> 2;
    const int t = lane & 3;

    const __half* Ab  = A  + (size_t)blockIdx.y * 128 * K;
    const __half* BTb = BT + (size_t)blockIdx.x * 128 * K;

    auto load_stage = [&](int s, int k0) {
        uint32_t sa = smb + (uint32_t)(s * GSTAGE_BYTES);
        uint32_t sb = sa + 128u * 80u;
#pragma unroll
        for (int p = 0; p < 2; p++) {
            int idx = tid + p * 256;
            int r = idx >> 2, c16 = idx & 3;
            cpa16(sa + (uint32_t)(r * 80 + c16 * 16),
                  Ab + (size_t)r * K + k0 + c16 * 8);
        }
#pragma unroll
        for (int p = 0; p < 2; p++) {
            int idx = tid + p * 256;
            int r = idx >> 2, c16 = idx & 3;
            cpa16(sb + (uint32_t)(r * 80 + c16 * 16),
                  BTb + (size_t)r * K + k0 + c16 * 8);
        }
        cpa_commit();
    };

    // ldmatrix per-lane byte offsets (relative to stage A / B bases)
    // A 16x16 tile at (wm + mi*16, kh): lane -> row (lane&15), colblk (lane>>4)*8
    uint32_t a_off[2];
#pragma unroll
    for (int mi = 0; mi < 2; mi++)
        a_off[mi] = (uint32_t)(((wm + mi * 16 + (lane & 15)) * HSTR +
                                ((lane >> 4) << 3)) * 2);
    // B pair of n-tiles at (wn + nip*16, kh):
    // lanes 0-7: rows n0..n0+7 colblk 0 ; 8-15: same rows colblk 8;
    // 16-23: rows n0+8.. colblk 0 ; 24-31: colblk 8
    uint32_t b_off[4];
#pragma unroll
    for (int nip = 0; nip < 4; nip++)
        b_off[nip] = (uint32_t)(((wn + nip * 16 + ((lane >> 4) << 3) +
                                  (lane & 7)) * HSTR +
                                 (((lane >> 3) & 1) << 3)) * 2);

    float acc[2][8][4];
#pragma unroll
    for (int mi = 0; mi < 2; mi++)
#pragma unroll
        for (int ni = 0; ni < 8; ni++)
#pragma unroll
            for (int q = 0; q < 4; q++) acc[mi][ni][q] = 0.f;

    const int NIT = K / 32;
    load_stage(0, 0);
    load_stage(1, 32);

    int stg = 0;
    for (int it = 0; it < NIT; it++) {
        if (it + 1 < NIT) cpa_wait<1>(); else cpa_wait<0>();
        __syncthreads();
        if (it + 2 < NIT) load_stage((stg + 2) % GNSTG, (it + 2) * 32);

        const uint32_t sa = smb + (uint32_t)(stg * GSTAGE_BYTES);
        const uint32_t sb = sa + 128u * 80u;

#pragma unroll
        for (int ks = 0; ks < 2; ks++) {
            const uint32_t khb = (uint32_t)(ks * 16 * 2);
            uint32_t af[2][4];
            ldsm_x4(af[0], sa + a_off[0] + khb);
            ldsm_x4(af[1], sa + a_off[1] + khb);
            uint32_t bf[4][4];   // [nip][b0(ni), b1(ni), b0(ni+1), b1(ni+1)]
#pragma unroll
            for (int nip = 0; nip < 4; nip++)
                ldsm_x4(bf[nip], sb + b_off[nip] + khb);
#pragma unroll
            for (int mi = 0; mi < 2; mi++)
#pragma unroll
                for (int nip = 0; nip < 4; nip++) {
                    mma_f16(acc[mi][2 * nip],     af[mi], bf[nip]);
                    mma_f16(acc[mi][2 * nip + 1], af[mi], bf[nip] + 2);
                }
        }
        stg = (stg + 1) % GNSTG;
    }

    const int row0 = blockIdx.y * 128 + wm;
    const int col0 = blockIdx.x * 128 + wn;
#pragma unroll
    for (int mi = 0; mi < 2; mi++) {
        int r = row0 + mi * 16 + g;
#pragma unroll
        for (int ni = 0; ni < 8; ni++) {
            int c = col0 + ni * 8 + t * 2;
            if (Ch) {
                *reinterpret_cast<uint32_t*>(Ch + (size_t)r * N + c) =
                    packh2(acc[mi][ni][0], acc[mi][ni][1]);
                *reinterpret_cast<uint32_t*>(Ch + (size_t)(r + 8) * N + c) =
                    packh2(acc[mi][ni][2], acc[mi][ni][3]);
            } else {
                float b0 = 0.f, b1 = 0.f;
                if (bias) { b0 = bias[c]; b1 = bias[c + 1]; }
                *reinterpret_cast<float2*>(Cf + (size_t)r * N + c) =
                    make_float2(acc[mi][ni][0] + b0, acc[mi][ni][1] + b1);
                *reinterpret_cast<float2*>(Cf + (size_t)(r + 8) * N + c) =
                    make_float2(acc[mi][ni][2] + b0, acc[mi][ni][3] + b1);
            }
        }
    }
}

// ---------------------------------------------------------------------------
// fp16 flash attention. Q-tile 128, KV-tile 64, 8 warps (16 Q rows each).
// P register-resident; K frags via ldmatrix.x4 (144B stride conflict-free);
// V frags via ldmatrix.x4.trans. K/V double-buffered cp.async.
// ---------------------------------------------------------------------------
#define ASTRH 72
#define BLKQ 128
#define KVSTG_BYTES (2 * 64 * ASTRH * 2)   // K+V per stage = 18432
#define ATTN_SMEM_BYTES (BLKQ * ASTRH * 2 + 2 * KVSTG_BYTES)

__global__ void __launch_bounds__(256)
attn_f16_kernel(const __half* __restrict__ qkv, __half* __restrict__ out)
{
    extern __shared__ char asm_[];
    __half* sQ = (__half*)asm_;
    const uint32_t sQb  = smem_u32(sQ);
    const uint32_t sKVb = sQb + BLKQ * ASTRH * 2;

    const int tid = threadIdx.x;
    const int lane = tid & 31;
    const int warp = tid >> 5;
    const int g = lane >> 2;
    const int t = lane & 3;
    const int m0 = warp * 16;

    const int qt = (int)(gridDim.x - 1) - (int)blockIdx.x;  // heavy first
    const int bh = blockIdx.y;
    const int b = bh >> 4, h = bh & 15;
    const __half* base = qkv + (size_t)b * LSEQ * QKVN + h * HDIM;
    const int q0 = qt * BLKQ;
    const int nkv = 2 * qt + 2;

    auto load_kv = [&](int kt, int stg) {
        uint32_t kb = sKVb + (uint32_t)(stg * KVSTG_BYTES);
        uint32_t vb = kb + 64u * ASTRH * 2u;
        const int k0 = kt * 64;
#pragma unroll
        for (int p = 0; p < 2; p++) {
            int idx = tid + p * 256;
            int r = idx >> 3, c16 = idx & 7;
            const __half* rp = base + (size_t)(k0 + r) * QKVN + c16 * 8;
            cpa16(kb + (uint32_t)(r * 144 + c16 * 16), rp + DMODEL);
            cpa16(vb + (uint32_t)(r * 144 + c16 * 16), rp + 2 * DMODEL);
        }
        cpa_commit();
    };

    // Q load (own group), then KV stage 0
#pragma unroll
    for (int p = 0; p < 4; p++) {
        int idx = tid + p * 256;
        int r = idx >> 3, c16 = idx & 7;
        cpa16(sQb + (uint32_t)(r * 144 + c16 * 16),
              base + (size_t)(q0 + r) * QKVN + c16 * 8);
    }
    cpa_commit();
    load_kv(0, 0);

    cpa_wait<1>();   // Q landed
    __syncthreads();

    // Hoist Q fragments via ldmatrix, then scale by 0.125 (exact in fp16)
    uint32_t aq[4][4];
    {
        uint32_t q_off = (uint32_t)(((m0 + (lane & 15)) * ASTRH +
                                     ((lane >> 4) << 3)) * 2);
        const __half2 sc = __float2half2_rn(0.125f);
#pragma unroll
        for (int ks = 0; ks < 4; ks++) {
            ldsm_x4(aq[ks], sQb + q_off + (uint32_t)(ks * 16 * 2));
#pragma unroll
            for (int q = 0; q < 4; q++) {
                __half2 v = __hmul2(*reinterpret_cast<__half2*>(&aq[ks][q]), sc);
                aq[ks][q] = *reinterpret_cast<uint32_t*>(&v);
            }
        }
    }

    // K-fragment ldmatrix lane offset (pair of n-tiles nip at k-block kh)
    uint32_t k_off[4];
#pragma unroll
    for (int nip = 0; nip < 4; nip++)
        k_off[nip] = (uint32_t)(((nip * 16 + ((lane >> 4) << 3) +
                                  (lane & 7)) * ASTRH +
                                 (((lane >> 3) & 1) << 3)) * 2);

    float o[8][4];
#pragma unroll
    for (int nt = 0; nt < 8; nt++)
#pragma unroll
        for (int q = 0; q < 4; q++) o[nt][q] = 0.f;
    float mr0 = -1e30f, mr1 = -1e30f, l0 = 0.f, l1 = 0.f;

    const int row0g = q0 + m0 + g;
    const int row1g = row0g + 8;

    for (int kt = 0; kt < nkv; kt++) {
        const int k0 = kt * 64;
        __syncthreads();   // all warps done reading previous stage

        if (kt + 1 < nkv) {
            load_kv(kt + 1, (kt + 1) & 1);
            cpa_wait<1>();
        } else {
            cpa_wait<0>();
        }
        __syncthreads();

        const uint32_t kvb = sKVb + (uint32_t)((kt & 1) * KVSTG_BYTES);
        const uint32_t sVb = kvb + 64u * ASTRH * 2u;

        // S = (Q*scale) @ K^T : 16x64 per warp, 32 MMAs
        float s[8][4];
#pragma unroll
        for (int nt = 0; nt < 8; nt++)
#pragma unroll
            for (int q = 0; q < 4; q++) s[nt][q] = 0.f;

#pragma unroll
        for (int ks = 0; ks < 4; ks++) {
            const uint32_t khb = (uint32_t)(ks * 16 * 2);
#pragma unroll
            for (int nip = 0; nip < 4; nip++) {
                uint32_t bf[4];
                ldsm_x4(bf, kvb + k_off[nip] + khb);
                mma_f16(s[2 * nip],     aq[ks], bf);
                mma_f16(s[2 * nip + 1], aq[ks], bf + 2);
            }
        }

        // Causal mask (diagonal tiles only)
        if (kt >= 2 * qt) {
#pragma unroll
            for (int nt = 0; nt < 8; nt++) {
                int cb = k0 + nt * 8 + 2 * t;
#pragma unroll
                for (int q = 0; q < 2; q++) {
                    if (cb + q > row0g) s[nt][q] = -1e30f;
                    if (cb + q > row1g) s[nt][2 + q] = -1e30f;
                }
            }
        }

        // Online softmax (rows g and g+8; quad-reduce over t lanes)
        float mt0 = -1e30f, mt1 = -1e30f;
#pragma unroll
        for (int nt = 0; nt < 8; nt++) {
            mt0 = fmaxf(mt0, fmaxf(s[nt][0], s[nt][1]));
            mt1 = fmaxf(mt1, fmaxf(s[nt][2], s[nt][3]));
        }
        mt0 = fmaxf(mt0, __shfl_xor_sync(0xffffffffu, mt0, 1));
        mt0 = fmaxf(mt0, __shfl_xor_sync(0xffffffffu, mt0, 2));
        mt1 = fmaxf(mt1, __shfl_xor_sync(0xffffffffu, mt1, 1));
        mt1 = fmaxf(mt1, __shfl_xor_sync(0xffffffffu, mt1, 2));

        float mn0 = fmaxf(mr0, mt0), mn1 = fmaxf(mr1, mt1);
        float cr0 = __expf(mr0 - mn0), cr1 = __expf(mr1 - mn1);
        mr0 = mn0; mr1 = mn1;

        float rs0 = 0.f, rs1 = 0.f;
#pragma unroll
        for (int nt = 0; nt < 8; nt++) {
            s[nt][0] = __expf(s[nt][0] - mn0);
            s[nt][1] = __expf(s[nt][1] - mn0);
            s[nt][2] = __expf(s[nt][2] - mn1);
            s[nt][3] = __expf(s[nt][3] - mn1);
            rs0 += s[nt][0] + s[nt][1];
            rs1 += s[nt][2] + s[nt][3];
        }
        rs0 += __shfl_xor_sync(0xffffffffu, rs0, 1);
        rs0 += __shfl_xor_sync(0xffffffffu, rs0, 2);
        rs1 += __shfl_xor_sync(0xffffffffu, rs1, 1);
        rs1 += __shfl_xor_sync(0xffffffffu, rs1, 2);
        l0 = l0 * cr0 + rs0;
        l1 = l1 * cr1 + rs1;

#pragma unroll
        for (int nt = 0; nt < 8; nt++) {
            o[nt][0] *= cr0; o[nt][1] *= cr0;
            o[nt][2] *= cr1; o[nt][3] *= cr1;
        }

        // Pack P fragments in registers
        uint32_t ap[4][4];
#pragma unroll
        for (int ks = 0; ks < 4; ks++) {
            ap[ks][0] = packh2(s[2 * ks][0], s[2 * ks][1]);
            ap[ks][1] = packh2(s[2 * ks][2], s[2 * ks][3]);
            ap[ks][2] = packh2(s[2 * ks + 1][0], s[2 * ks + 1][1]);
            ap[ks][3] = packh2(s[2 * ks + 1][2], s[2 * ks + 1][3]);
        }

        // O += P @ V, V frags via ldmatrix.x4.trans
#pragma unroll
        for (int ks = 0; ks < 4; ks++) {
#pragma unroll
            for (int ntp = 0; ntp < 4; ntp++) {
                uint32_t bv[4];
                uint32_t vaddr = sVb +
                    (uint32_t)(((16 * ks + (lane & 15)) * ASTRH +
                                ntp * 16 + ((lane >> 4) << 3)) * 2);
                ldsm_x4_t(bv, vaddr);
                mma_f16(o[2 * ntp],     ap[ks], bv);
                mma_f16(o[2 * ntp + 1], ap[ks], bv + 2);
            }
        }
    }

    // Epilogue: normalize, write fp16 (B*L, D)
    float inv0 = 1.0f / l0, inv1 = 1.0f / l1;
    __half* ob0 = out + (size_t)(b * LSEQ + row0g) * DMODEL + h * HDIM + 2 * t;
    __half* ob1 = out + (size_t)(b * LSEQ + row1g) * DMODEL + h * HDIM + 2 * t;
#pragma unroll
    for (int nt = 0; nt < 8; nt++) {
        *reinterpret_cast<uint32_t*>(ob0 + nt * 8) =
            packh2(o[nt][0] * inv0, o[nt][1] * inv0);
        *reinterpret_cast<uint32_t*>(ob1 + nt * 8) =
            packh2(o[nt][2] * inv1, o[nt][3] * inv1);
    }
}

// ---------------------------------------------------------------------------
extern "C" void kernel_launch(void* const* d_in, const int* in_sizes, int n_in,
                              void* d_out, int out_size)
{
    (void)in_sizes; (void)n_in; (void)out_size;
    const float* x      = (const float*)d_in[0];
    // d_in[1] = attn_mask (always causal triu(k=1); implemented directly)
    const float* w_qkv  = (const float*)d_in[2];
    const float* w_proj = (const float*)d_in[3];
    const float* b_proj = (const float*)d_in[4];
    float* out = (float*)d_out;

    __half *xh, *wqkvT, *wprojT, *qkvh, *attnh;
    cudaGetSymbolAddress((void**)&xh, g_x_h);
    cudaGetSymbolAddress((void**)&wqkvT, g_wqkvT_h);
    cudaGetSymbolAddress((void**)&wprojT, g_wprojT_h);
    cudaGetSymbolAddress((void**)&qkvh, g_qkv_h);
    cudaGetSymbolAddress((void**)&attnh, g_attn_h);

    cudaFuncSetAttribute(gemm_f16_kernel,
                         cudaFuncAttributeMaxDynamicSharedMemorySize,
                         GEMM_SMEM_BYTES);
    cudaFuncSetAttribute(attn_f16_kernel,
                         cudaFuncAttributeMaxDynamicSharedMemorySize,
                         ATTN_SMEM_BYTES);

    // 0) Pre-pass: fp16 convert x; transpose+convert weights to [N][K]
    {
        int n4x = MROWS * DMODEL / 4;
        f2h_kernel<<<(n4x + 255) / 256, 256>>>(
            (const float4*)x, (uint2*)xh, n4x);
        dim3 tb(32, 8);
        transpose_h_kernel<<<dim3(QKVN / 32, DMODEL / 32), tb>>>(
            w_qkv, wqkvT, DMODEL, QKVN);
        transpose_h_kernel<<<dim3(DMODEL / 32, DMODEL / 32), tb>>>(
            w_proj, wprojT, DMODEL, DMODEL);
    }

    // 1) QKV GEMM: (8192,1024) @ (1024,3072), fp16 out
    {
        dim3 grid(QKVN / 128, MROWS / 128);
        gemm_f16_kernel<<<grid, 256, GEMM_SMEM_BYTES>>>(
            xh, wqkvT, nullptr, qkvh, MROWS, QKVN, DMODEL, nullptr);
    }
    // 2) Causal flash attention (fp16 MMA, register P, ldmatrix everywhere)
    {
        dim3 grid(LSEQ / BLKQ, BB * NH);
        attn_f16_kernel<<<grid, 256, ATTN_SMEM_BYTES>>>(qkvh, attnh);
    }
    // 3) Output projection + bias: (8192,1024) @ (1024,1024), fp32 out
    {
        dim3 grid(DMODEL / 128, MROWS / 128);
        gemm_f16_kernel<<<grid, 256, GEMM_SMEM_BYTES>>>(
            attnh, wprojT, out, nullptr, MROWS, DMODEL, DMODEL, b_proj);
    }
}

// round 13
// speedup vs baseline: 2.1873x; 1.0732x over previous
#include <cuda_runtime.h>
#include <cuda_fp16.h>
#include <cstddef>
#include <cstdint>
#include <math.h>

// Problem constants
#define BB 4
#define LSEQ 2048
#define DMODEL 1024
#define NH 16
#define HDIM 64
#define MROWS (BB * LSEQ)      // 8192
#define QKVN (3 * DMODEL)      // 3072

// Scratch (static device arrays; no allocation APIs allowed)
__device__ __half g_x_h[(size_t)MROWS * DMODEL];
__device__ __half g_wqkvT_h[(size_t)QKVN * DMODEL];   // (3072,1024) K-major
__device__ __half g_wprojT_h[(size_t)DMODEL * DMODEL];
__device__ __half g_qkv_h[(size_t)MROWS * QKVN];
__device__ __half g_attn_h[(size_t)MROWS * DMODEL];

// ---- fp16 MMA m16n8k16, fp32 accumulate ----------------------------------
__device__ __forceinline__ void mma_f16(float* d, const uint32_t* a,
                                        const uint32_t* b) {
    asm volatile(
        "mma.sync.aligned.m16n8k16.row.col.f32.f16.f16.f32 "
        "{%0,%1,%2,%3}, {%4,%5,%6,%7}, {%8,%9}, {%0,%1,%2,%3};\n"
        : "+f"(d[0]), "+f"(d[1]), "+f"(d[2]), "+f"(d[3])
        : "r"(a[0]), "r"(a[1]), "r"(a[2]), "r"(a[3]), "r"(b[0]), "r"(b[1]));
}

__device__ __forceinline__ void ldsm_x4(uint32_t* r, uint32_t addr) {
    asm volatile(
        "ldmatrix.sync.aligned.m8n8.x4.shared.b16 {%0,%1,%2,%3}, [%4];"
        : "=r"(r[0]), "=r"(r[1]), "=r"(r[2]), "=r"(r[3]) : "r"(addr));
}
__device__ __forceinline__ void ldsm_x4_t(uint32_t* r, uint32_t addr) {
    asm volatile(
        "ldmatrix.sync.aligned.m8n8.x4.trans.shared.b16 {%0,%1,%2,%3}, [%4];"
        : "=r"(r[0]), "=r"(r[1]), "=r"(r[2]), "=r"(r[3]) : "r"(addr));
}

__device__ __forceinline__ void cpa16(uint32_t dst_smem, const void* src) {
    asm volatile("cp.async.cg.shared.global [%0], [%1], 16;\n"
                 :: "r"(dst_smem), "l"(src));
}
__device__ __forceinline__ void cpa_commit() {
    asm volatile("cp.async.commit_group;\n");
}
template <int N>
__device__ __forceinline__ void cpa_wait() {
    asm volatile("cp.async.wait_group %0;\n" :: "n"(N));
}
__device__ __forceinline__ uint32_t smem_u32(const void* p) {
    return (uint32_t)__cvta_generic_to_shared(p);
}
__device__ __forceinline__ uint32_t packh2(float lo, float hi) {
    __half2 h = __floats2half2_rn(lo, hi);
    return *reinterpret_cast<uint32_t*>(&h);
}

// ---------------------------------------------------------------------------
// Pre-pass kernels: fp32 -> fp16 convert / transpose
// ---------------------------------------------------------------------------
__global__ void f2h_kernel(const float4* __restrict__ in,
                           uint2* __restrict__ out, int n4)
{
    int i = blockIdx.x * blockDim.x + threadIdx.x;
    if (i < n4) {
        float4 v = in[i];
        out[i] = make_uint2(packh2(v.x, v.y), packh2(v.z, v.w));
    }
}

// in (R, C) fp32 -> out (C, R) fp16
__global__ void transpose_h_kernel(const float* __restrict__ in,
                                   __half* __restrict__ out, int R, int C)
{
    __shared__ float tile[32][33];
    int gx = blockIdx.x * 32, gy = blockIdx.y * 32;
    int tx = threadIdx.x, ty = threadIdx.y;
#pragma unroll
    for (int j = 0; j < 4; j++)
        tile[ty + j * 8][tx] = in[(size_t)(gy + ty + j * 8) * C + gx + tx];
    __syncthreads();
#pragma unroll
    for (int j = 0; j < 4; j++)
        out[(size_t)(gx + ty + j * 8) * R + gy + tx] =
            __float2half(tile[tx][ty + j * 8]);
}

// ---------------------------------------------------------------------------
// fp16 tensor-core GEMM: C[M,N] = A[M,K] @ BT[N,K]^T (+bias).
// CTA tile 128x128, BK=64 halves (144B rows, ldmatrix conflict-free),
// 8 warps (4M x 2N), warp tile 32x64. 3-stage cp.async pipeline;
// 16 barriers per K=1024 instead of 32.
// ---------------------------------------------------------------------------
#define HSTR 72
#define GNSTG 3
#define GSTAGE_BYTES (256 * HSTR * 2)   // 36864
#define GEMM_SMEM_BYTES (GNSTG * GSTAGE_BYTES)

__global__ void __launch_bounds__(256, 2)
gemm_f16_kernel(const __half* __restrict__ A, const __half* __restrict__ BT,
                float* __restrict__ Cf, __half* __restrict__ Ch,
                int M, int N, int K, const float* __restrict__ bias)
{
    extern __shared__ char gsm[];
    const uint32_t smb = smem_u32(gsm);

    const int tid = threadIdx.x;
    const int lane = tid & 31;
    const int warp = tid >> 5;
    const int wm = (warp & 3) * 32;
    const int wn = (warp >> 2) * 64;
    const int g = lane >> 2;
    const int t = lane & 3;

    const __half* Ab  = A  + (size_t)blockIdx.y * 128 * K;
    const __half* BTb = BT + (size_t)blockIdx.x * 128 * K;

    // 128 rows x 64 halves per operand: 8 x 16B chunks/row -> 4 cpa16/thread
    auto load_stage = [&](int s, int k0) {
        uint32_t sa = smb + (uint32_t)(s * GSTAGE_BYTES);
        uint32_t sb = sa + 128u * 144u;
#pragma unroll
        for (int p = 0; p < 4; p++) {
            int idx = tid + p * 256;
            int r = idx >> 3, c16 = idx & 7;
            cpa16(sa + (uint32_t)(r * 144 + c16 * 16),
                  Ab + (size_t)r * K + k0 + c16 * 8);
        }
#pragma unroll
        for (int p = 0; p < 4; p++) {
            int idx = tid + p * 256;
            int r = idx >> 3, c16 = idx & 7;
            cpa16(sb + (uint32_t)(r * 144 + c16 * 16),
                  BTb + (size_t)r * K + k0 + c16 * 8);
        }
        cpa_commit();
    };

    // ldmatrix per-lane byte offsets
    uint32_t a_off[2];
#pragma unroll
    for (int mi = 0; mi < 2; mi++)
        a_off[mi] = (uint32_t)(((wm + mi * 16 + (lane & 15)) * HSTR +
                                ((lane >> 4) << 3)) * 2);
    uint32_t b_off[4];
#pragma unroll
    for (int nip = 0; nip < 4; nip++)
        b_off[nip] = (uint32_t)(((wn + nip * 16 + ((lane >> 4) << 3) +
                                  (lane & 7)) * HSTR +
                                 (((lane >> 3) & 1) << 3)) * 2);

    float acc[2][8][4];
#pragma unroll
    for (int mi = 0; mi < 2; mi++)
#pragma unroll
        for (int ni = 0; ni < 8; ni++)
#pragma unroll
            for (int q = 0; q < 4; q++) acc[mi][ni][q] = 0.f;

    const int NIT = K / 64;
    load_stage(0, 0);
    load_stage(1, 64);

    int stg = 0;
    for (int it = 0; it < NIT; it++) {
        if (it + 1 < NIT) cpa_wait<1>(); else cpa_wait<0>();
        __syncthreads();
        if (it + 2 < NIT) load_stage((stg + 2) % GNSTG, (it + 2) * 64);

        const uint32_t sa = smb + (uint32_t)(stg * GSTAGE_BYTES);
        const uint32_t sb = sa + 128u * 144u;

#pragma unroll
        for (int ks = 0; ks < 4; ks++) {
            const uint32_t khb = (uint32_t)(ks * 16 * 2);
            uint32_t af[2][4];
            ldsm_x4(af[0], sa + a_off[0] + khb);
            ldsm_x4(af[1], sa + a_off[1] + khb);
            uint32_t bf[4][4];
#pragma unroll
            for (int nip = 0; nip < 4; nip++)
                ldsm_x4(bf[nip], sb + b_off[nip] + khb);
#pragma unroll
            for (int mi = 0; mi < 2; mi++)
#pragma unroll
                for (int nip = 0; nip < 4; nip++) {
                    mma_f16(acc[mi][2 * nip],     af[mi], bf[nip]);
                    mma_f16(acc[mi][2 * nip + 1], af[mi], bf[nip] + 2);
                }
        }
        stg = (stg + 1) % GNSTG;
    }

    const int row0 = blockIdx.y * 128 + wm;
    const int col0 = blockIdx.x * 128 + wn;
#pragma unroll
    for (int mi = 0; mi < 2; mi++) {
        int r = row0 + mi * 16 + g;
#pragma unroll
        for (int ni = 0; ni < 8; ni++) {
            int c = col0 + ni * 8 + t * 2;
            if (Ch) {
                *reinterpret_cast<uint32_t*>(Ch + (size_t)r * N + c) =
                    packh2(acc[mi][ni][0], acc[mi][ni][1]);
                *reinterpret_cast<uint32_t*>(Ch + (size_t)(r + 8) * N + c) =
                    packh2(acc[mi][ni][2], acc[mi][ni][3]);
            } else {
                float b0 = 0.f, b1 = 0.f;
                if (bias) { b0 = bias[c]; b1 = bias[c + 1]; }
                *reinterpret_cast<float2*>(Cf + (size_t)r * N + c) =
                    make_float2(acc[mi][ni][0] + b0, acc[mi][ni][1] + b1);
                *reinterpret_cast<float2*>(Cf + (size_t)(r + 8) * N + c) =
                    make_float2(acc[mi][ni][2] + b0, acc[mi][ni][3] + b1);
            }
        }
    }
}

// ---------------------------------------------------------------------------
// fp16 flash attention. Q-tile 128, KV-tile 64, 8 warps (16 Q rows each).
// P register-resident; K frags via ldmatrix.x4 (144B stride conflict-free);
// V frags via ldmatrix.x4.trans. K/V double-buffered cp.async.
// ---------------------------------------------------------------------------
#define ASTRH 72
#define BLKQ 128
#define KVSTG_BYTES (2 * 64 * ASTRH * 2)   // K+V per stage = 18432
#define ATTN_SMEM_BYTES (BLKQ * ASTRH * 2 + 2 * KVSTG_BYTES)

__global__ void __launch_bounds__(256)
attn_f16_kernel(const __half* __restrict__ qkv, __half* __restrict__ out)
{
    extern __shared__ char asm_[];
    __half* sQ = (__half*)asm_;
    const uint32_t sQb  = smem_u32(sQ);
    const uint32_t sKVb = sQb + BLKQ * ASTRH * 2;

    const int tid = threadIdx.x;
    const int lane = tid & 31;
    const int warp = tid >> 5;
    const int g = lane >> 2;
    const int t = lane & 3;
    const int m0 = warp * 16;

    const int qt = (int)(gridDim.x - 1) - (int)blockIdx.x;  // heavy first
    const int bh = blockIdx.y;
    const int b = bh >> 4, h = bh & 15;
    const __half* base = qkv + (size_t)b * LSEQ * QKVN + h * HDIM;
    const int q0 = qt * BLKQ;
    const int nkv = 2 * qt + 2;

    auto load_kv = [&](int kt, int stg) {
        uint32_t kb = sKVb + (uint32_t)(stg * KVSTG_BYTES);
        uint32_t vb = kb + 64u * ASTRH * 2u;
        const int k0 = kt * 64;
#pragma unroll
        for (int p = 0; p < 2; p++) {
            int idx = tid + p * 256;
            int r = idx >> 3, c16 = idx & 7;
            const __half* rp = base + (size_t)(k0 + r) * QKVN + c16 * 8;
            cpa16(kb + (uint32_t)(r * 144 + c16 * 16), rp + DMODEL);
            cpa16(vb + (uint32_t)(r * 144 + c16 * 16), rp + 2 * DMODEL);
        }
        cpa_commit();
    };

    // Q load (own group), then KV stage 0
#pragma unroll
    for (int p = 0; p < 4; p++) {
        int idx = tid + p * 256;
        int r = idx >> 3, c16 = idx & 7;
        cpa16(sQb + (uint32_t)(r * 144 + c16 * 16),
              base + (size_t)(q0 + r) * QKVN + c16 * 8);
    }
    cpa_commit();
    load_kv(0, 0);

    cpa_wait<1>();   // Q landed
    __syncthreads();

    // Hoist Q fragments via ldmatrix, then scale by 0.125 (exact in fp16)
    uint32_t aq[4][4];
    {
        uint32_t q_off = (uint32_t)(((m0 + (lane & 15)) * ASTRH +
                                     ((lane >> 4) << 3)) * 2);
        const __half2 sc = __float2half2_rn(0.125f);
#pragma unroll
        for (int ks = 0; ks < 4; ks++) {
            ldsm_x4(aq[ks], sQb + q_off + (uint32_t)(ks * 16 * 2));
#pragma unroll
            for (int q = 0; q < 4; q++) {
                __half2 v = __hmul2(*reinterpret_cast<__half2*>(&aq[ks][q]), sc);
                aq[ks][q] = *reinterpret_cast<uint32_t*>(&v);
            }
        }
    }

    // K-fragment ldmatrix lane offset
    uint32_t k_off[4];
#pragma unroll
    for (int nip = 0; nip < 4; nip++)
        k_off[nip] = (uint32_t)(((nip * 16 + ((lane >> 4) << 3) +
                                  (lane & 7)) * ASTRH +
                                 (((lane >> 3) & 1) << 3)) * 2);

    float o[8][4];
#pragma unroll
    for (int nt = 0; nt < 8; nt++)
#pragma unroll
        for (int q = 0; q < 4; q++) o[nt][q] = 0.f;
    float mr0 = -1e30f, mr1 = -1e30f, l0 = 0.f, l1 = 0.f;

    const int row0g = q0 + m0 + g;
    const int row1g = row0g + 8;

    for (int kt = 0; kt < nkv; kt++) {
        const int k0 = kt * 64;
        __syncthreads();   // all warps done reading previous stage

        if (kt + 1 < nkv) {
            load_kv(kt + 1, (kt + 1) & 1);
            cpa_wait<1>();
        } else {
            cpa_wait<0>();
        }
        __syncthreads();

        const uint32_t kvb = sKVb + (uint32_t)((kt & 1) * KVSTG_BYTES);
        const uint32_t sVb = kvb + 64u * ASTRH * 2u;

        // S = (Q*scale) @ K^T : 16x64 per warp, 32 MMAs
        float s[8][4];
#pragma unroll
        for (int nt = 0; nt < 8; nt++)
#pragma unroll
            for (int q = 0; q < 4; q++) s[nt][q] = 0.f;

#pragma unroll
        for (int ks = 0; ks < 4; ks++) {
            const uint32_t khb = (uint32_t)(ks * 16 * 2);
#pragma unroll
            for (int nip = 0; nip < 4; nip++) {
                uint32_t bf[4];
                ldsm_x4(bf, kvb + k_off[nip] + khb);
                mma_f16(s[2 * nip],     aq[ks], bf);
                mma_f16(s[2 * nip + 1], aq[ks], bf + 2);
            }
        }

        // Causal mask (diagonal tiles only)
        if (kt >= 2 * qt) {
#pragma unroll
            for (int nt = 0; nt < 8; nt++) {
                int cb = k0 + nt * 8 + 2 * t;
#pragma unroll
                for (int q = 0; q < 2; q++) {
                    if (cb + q > row0g) s[nt][q] = -1e30f;
                    if (cb + q > row1g) s[nt][2 + q] = -1e30f;
                }
            }
        }

        // Online softmax (rows g and g+8; quad-reduce over t lanes)
        float mt0 = -1e30f, mt1 = -1e30f;
#pragma unroll
        for (int nt = 0; nt < 8; nt++) {
            mt0 = fmaxf(mt0, fmaxf(s[nt][0], s[nt][1]));
            mt1 = fmaxf(mt1, fmaxf(s[nt][2], s[nt][3]));
        }
        mt0 = fmaxf(mt0, __shfl_xor_sync(0xffffffffu, mt0, 1));
        mt0 = fmaxf(mt0, __shfl_xor_sync(0xffffffffu, mt0, 2));
        mt1 = fmaxf(mt1, __shfl_xor_sync(0xffffffffu, mt1, 1));
        mt1 = fmaxf(mt1, __shfl_xor_sync(0xffffffffu, mt1, 2));

        float mn0 = fmaxf(mr0, mt0), mn1 = fmaxf(mr1, mt1);
        float cr0 = __expf(mr0 - mn0), cr1 = __expf(mr1 - mn1);
        mr0 = mn0; mr1 = mn1;

        float rs0 = 0.f, rs1 = 0.f;
#pragma unroll
        for (int nt = 0; nt < 8; nt++) {
            s[nt][0] = __expf(s[nt][0] - mn0);
            s[nt][1] = __expf(s[nt][1] - mn0);
            s[nt][2] = __expf(s[nt][2] - mn1);
            s[nt][3] = __expf(s[nt][3] - mn1);
            rs0 += s[nt][0] + s[nt][1];
            rs1 += s[nt][2] + s[nt][3];
        }
        rs0 += __shfl_xor_sync(0xffffffffu, rs0, 1);
        rs0 += __shfl_xor_sync(0xffffffffu, rs0, 2);
        rs1 += __shfl_xor_sync(0xffffffffu, rs1, 1);
        rs1 += __shfl_xor_sync(0xffffffffu, rs1, 2);
        l0 = l0 * cr0 + rs0;
        l1 = l1 * cr1 + rs1;

#pragma unroll
        for (int nt = 0; nt < 8; nt++) {
            o[nt][0] *= cr0; o[nt][1] *= cr0;
            o[nt][2] *= cr1; o[nt][3] *= cr1;
        }

        // Pack P fragments in registers
        uint32_t ap[4][4];
#pragma unroll
        for (int ks = 0; ks < 4; ks++) {
            ap[ks][0] = packh2(s[2 * ks][0], s[2 * ks][1]);
            ap[ks][1] = packh2(s[2 * ks][2], s[2 * ks][3]);
            ap[ks][2] = packh2(s[2 * ks + 1][0], s[2 * ks + 1][1]);
            ap[ks][3] = packh2(s[2 * ks + 1][2], s[2 * ks + 1][3]);
        }

        // O += P @ V, V frags via ldmatrix.x4.trans
#pragma unroll
        for (int ks = 0; ks < 4; ks++) {
#pragma unroll
            for (int ntp = 0; ntp < 4; ntp++) {
                uint32_t bv[4];
                uint32_t vaddr = sVb +
                    (uint32_t)(((16 * ks + (lane & 15)) * ASTRH +
                                ntp * 16 + ((lane >> 4) << 3)) * 2);
                ldsm_x4_t(bv, vaddr);
                mma_f16(o[2 * ntp],     ap[ks], bv);
                mma_f16(o[2 * ntp + 1], ap[ks], bv + 2);
            }
        }
    }

    // Epilogue: normalize, write fp16 (B*L, D)
    float inv0 = 1.0f / l0, inv1 = 1.0f / l1;
    __half* ob0 = out + (size_t)(b * LSEQ + row0g) * DMODEL + h * HDIM + 2 * t;
    __half* ob1 = out + (size_t)(b * LSEQ + row1g) * DMODEL + h * HDIM + 2 * t;
#pragma unroll
    for (int nt = 0; nt < 8; nt++) {
        *reinterpret_cast<uint32_t*>(ob0 + nt * 8) =
            packh2(o[nt][0] * inv0, o[nt][1] * inv0);
        *reinterpret_cast<uint32_t*>(ob1 + nt * 8) =
            packh2(o[nt][2] * inv1, o[nt][3] * inv1);
    }
}

// ---------------------------------------------------------------------------
extern "C" void kernel_launch(void* const* d_in, const int* in_sizes, int n_in,
                              void* d_out, int out_size)
{
    (void)in_sizes; (void)n_in; (void)out_size;
    const float* x      = (const float*)d_in[0];
    // d_in[1] = attn_mask (always causal triu(k=1); implemented directly)
    const float* w_qkv  = (const float*)d_in[2];
    const float* w_proj = (const float*)d_in[3];
    const float* b_proj = (const float*)d_in[4];
    float* out = (float*)d_out;

    __half *xh, *wqkvT, *wprojT, *qkvh, *attnh;
    cudaGetSymbolAddress((void**)&xh, g_x_h);
    cudaGetSymbolAddress((void**)&wqkvT, g_wqkvT_h);
    cudaGetSymbolAddress((void**)&wprojT, g_wprojT_h);
    cudaGetSymbolAddress((void**)&qkvh, g_qkv_h);
    cudaGetSymbolAddress((void**)&attnh, g_attn_h);

    cudaFuncSetAttribute(gemm_f16_kernel,
                         cudaFuncAttributeMaxDynamicSharedMemorySize,
                         GEMM_SMEM_BYTES);
    cudaFuncSetAttribute(attn_f16_kernel,
                         cudaFuncAttributeMaxDynamicSharedMemorySize,
                         ATTN_SMEM_BYTES);

    // 0) Pre-pass: fp16 convert x; transpose+convert weights to [N][K]
    {
        int n4x = MROWS * DMODEL / 4;
        f2h_kernel<<<(n4x + 255) / 256, 256>>>(
            (const float4*)x, (uint2*)xh, n4x);
        dim3 tb(32, 8);
        transpose_h_kernel<<<dim3(QKVN / 32, DMODEL / 32), tb>>>(
            w_qkv, wqkvT, DMODEL, QKVN);
        transpose_h_kernel<<<dim3(DMODEL / 32, DMODEL / 32), tb>>>(
            w_proj, wprojT, DMODEL, DMODEL);
    }

    // 1) QKV GEMM: (8192,1024) @ (1024,3072), fp16 out
    {
        dim3 grid(QKVN / 128, MROWS / 128);
        gemm_f16_kernel<<<grid, 256, GEMM_SMEM_BYTES>>>(
            xh, wqkvT, nullptr, qkvh, MROWS, QKVN, DMODEL, nullptr);
    }
    // 2) Causal flash attention (fp16 MMA, register P, ldmatrix everywhere)
    {
        dim3 grid(LSEQ / BLKQ, BB * NH);
        attn_f16_kernel<<<grid, 256, ATTN_SMEM_BYTES>>>(qkvh, attnh);
    }
    // 3) Output projection + bias: (8192,1024) @ (1024,1024), fp32 out
    {
        dim3 grid(DMODEL / 128, MROWS / 128);
        gemm_f16_kernel<<<grid, 256, GEMM_SMEM_BYTES>>>(
            attnh, wprojT, out, nullptr, MROWS, DMODEL, DMODEL, b_proj);
    }
}